// round 11
// baseline (speedup 1.0000x reference)
#include <cuda_runtime.h>
#include <cuda_fp16.h>
#include <stdint.h>
#include <math.h>

#define T_SEQ 2048
#define D_EMB 2048
#define HD    128
#define NHEADS 16
#define QK_SCALE 0.08838834764831843f
#define WSCALE 256.0f
#define INV_WSCALE (1.0f / 256.0f)

// ---------------- scratch (no allocs allowed) ----------------
__device__ __half g_Xf[T_SEQ * D_EMB];
__device__ __half g_Rf[T_SEQ * D_EMB];
__device__ __half g_Wq[D_EMB * D_EMB];
__device__ __half g_Wk[D_EMB * D_EMB];
__device__ __half g_Wv[D_EMB * D_EMB];
__device__ __half g_Wo[D_EMB * D_EMB];
__device__ __half g_Qf[T_SEQ * D_EMB];
__device__ __half g_Kf[T_SEQ * D_EMB];
__device__ __half g_Vf[T_SEQ * D_EMB];

// ---------------- PTX helpers (base sm_103-legal only) ----------------
__device__ __forceinline__ uint32_t smem_u32(const void* p) {
    uint32_t a;
    asm("{ .reg .u64 t; cvta.to.shared.u64 t, %1; cvt.u32.u64 %0, t; }"
        : "=r"(a) : "l"(p));
    return a;
}
#define CP_ASYNC16(dst, src) \
    asm volatile("cp.async.cg.shared.global [%0], [%1], 16;" :: "r"(dst), "l"(src))
#define CP_COMMIT() asm volatile("cp.async.commit_group;" ::: "memory")
#define CP_WAIT(n) asm volatile("cp.async.wait_group %0;" :: "n"(n) : "memory")

__device__ __forceinline__ void ldsm_x4(uint32_t& r0, uint32_t& r1, uint32_t& r2,
                                        uint32_t& r3, uint32_t addr) {
    asm volatile("ldmatrix.sync.aligned.m8n8.x4.shared.b16 {%0,%1,%2,%3}, [%4];"
                 : "=r"(r0), "=r"(r1), "=r"(r2), "=r"(r3) : "r"(addr));
}
__device__ __forceinline__ void ldsm_x4_t(uint32_t& r0, uint32_t& r1, uint32_t& r2,
                                          uint32_t& r3, uint32_t addr) {
    asm volatile(
        "ldmatrix.sync.aligned.m8n8.x4.trans.shared.b16 {%0,%1,%2,%3}, [%4];"
        : "=r"(r0), "=r"(r1), "=r"(r2), "=r"(r3) : "r"(addr));
}
__device__ __forceinline__ void mma16816(float* c, const uint32_t* a,
                                         const uint32_t* b) {
    asm volatile(
        "mma.sync.aligned.m16n8k16.row.col.f32.f16.f16.f32 "
        "{%0,%1,%2,%3}, {%4,%5,%6,%7}, {%8,%9}, {%0,%1,%2,%3};"
        : "+f"(c[0]), "+f"(c[1]), "+f"(c[2]), "+f"(c[3])
        : "r"(a[0]), "r"(a[1]), "r"(a[2]), "r"(a[3]), "r"(b[0]), "r"(b[1]));
}
__device__ __forceinline__ uint32_t pack_f16(float x, float y) {
    __half2 h = __floats2half2_rn(x, y);
    return *reinterpret_cast<uint32_t*>(&h);
}

// ---------------- conversion kernels ----------------
__global__ __launch_bounds__(256) void convX(const float* __restrict__ A,
                                             __half* __restrict__ F) {
    const int i = blockIdx.x * 256 + threadIdx.x;
    float4 v = reinterpret_cast<const float4*>(A)[i];
    __half f[4] = {__float2half_rn(v.x), __float2half_rn(v.y),
                   __float2half_rn(v.z), __float2half_rn(v.w)};
    reinterpret_cast<uint2*>(F)[i] = *reinterpret_cast<uint2*>(f);
}

__global__ __launch_bounds__(256) void convW16all(
    const float* __restrict__ Wq, const float* __restrict__ Wk,
    const float* __restrict__ Wv, const float* __restrict__ Wo,
    __half* __restrict__ Hq, __half* __restrict__ Hk,
    __half* __restrict__ Hv, __half* __restrict__ Ho) {
    __shared__ float t[32][33];
    const int z = blockIdx.z;
    const float* W = (z == 0) ? Wq : (z == 1) ? Wk : (z == 2) ? Wv : Wo;
    __half* H = (z == 0) ? Hq : (z == 1) ? Hk : (z == 2) ? Hv : Ho;
    const int hd = (z == 3) ? D_EMB : HD;
    const int n  = (z == 3) ? 0 : (blockIdx.x >> 2);
    const int j0 = (z == 3) ? (blockIdx.x * 32) : ((blockIdx.x & 3) * 32);
    const int k0 = blockIdx.y * 32;
    const int tx = threadIdx.x, ty = threadIdx.y;
    const float* Wn = W + (size_t)n * D_EMB * hd;
#pragma unroll
    for (int y = ty; y < 32; y += 8) t[y][tx] = Wn[(size_t)(k0 + y) * hd + j0 + tx];
    __syncthreads();
#pragma unroll
    for (int y = ty; y < 32; y += 8) {
        H[(size_t)(n * hd + j0 + y) * D_EMB + k0 + tx] =
            __float2half_rn(t[tx][y] * WSCALE);
    }
}

// ---------------- 1-pass fp16 HMMA GEMM (warp 64x64, BK=64) ----------------
#define BM 128
#define BN 128
#define BK 64
#define STAGE_B 32768
#define GEMM_SMEM (3 * STAGE_B)

__device__ __forceinline__ uint32_t swz8(uint32_t base, int row, int chunk) {
    return base + (((row << 3) + (chunk ^ (row & 7))) << 4);
}

__device__ __forceinline__ void stage_tile64(uint32_t sbase,
                                             const __half* __restrict__ g,
                                             int row0, int k0, int tid) {
#pragma unroll
    for (int u = tid; u < 1024; u += 128) {
        const int row = u >> 3, ch = u & 7;
        const uint32_t dst = swz8(sbase, row, ch);
        const __half* src = g + (size_t)(row0 + row) * D_EMB + k0 + ch * 8;
        CP_ASYNC16(dst, src);
    }
}

__device__ __forceinline__ void stage_all(uint32_t sbase, const __half* Af,
                                          const __half* Bf, int bm, int bn,
                                          int k0, int tid) {
    stage_tile64(sbase + 0,     Af, bm, k0, tid);
    stage_tile64(sbase + 16384, Bf, bn, k0, tid);
    CP_COMMIT();
}

__device__ __forceinline__ void gemm_core1(
    uint32_t sb, const __half* Af, const __half* Bf, int bm, int bn, int tid,
    float acc[4][8][4]) {
    const int lane = tid & 31;
    const int wid = tid >> 5;
    const int wm = wid & 1;
    const int wn = wid >> 1;
    const int lr = lane & 7;
    const int lg = lane >> 3;

#pragma unroll
    for (int mt = 0; mt < 4; mt++)
#pragma unroll
        for (int nt = 0; nt < 8; nt++)
#pragma unroll
            for (int e = 0; e < 4; e++) acc[mt][nt][e] = 0.0f;

    stage_all(sb + 0 * STAGE_B, Af, Bf, bm, bn, 0, tid);
    stage_all(sb + 1 * STAGE_B, Af, Bf, bm, bn, BK, tid);

    const int NITER = D_EMB / BK;  // 32
    for (int c = 0; c < NITER; c++) {
        if (c == NITER - 1) {
            CP_WAIT(0);
        } else {
            CP_WAIT(1);
        }
        __syncthreads();
        if (c + 2 < NITER)
            stage_all(sb + ((c + 2) % 3) * STAGE_B, Af, Bf, bm, bn,
                      (c + 2) * BK, tid);

        const uint32_t sX = sb + (c % 3) * STAGE_B;
        const uint32_t sB = sX + 16384;

#pragma unroll
        for (int kk = 0; kk < 4; kk++) {
            uint32_t a4[4][4];
#pragma unroll
            for (int mt = 0; mt < 4; mt++) {
                const int row = wm * 64 + mt * 16 + lr + (lg & 1) * 8;
                const int ch = kk * 2 + (lg >> 1);
                ldsm_x4(a4[mt][0], a4[mt][1], a4[mt][2], a4[mt][3],
                        swz8(sX, row, ch));
            }
            uint32_t b4[8][2];
#pragma unroll
            for (int np = 0; np < 4; np++) {
                const int row = wn * 64 + np * 16 + lr + (lg >> 1) * 8;
                const int ch = kk * 2 + (lg & 1);
                ldsm_x4(b4[np * 2][0], b4[np * 2][1], b4[np * 2 + 1][0],
                        b4[np * 2 + 1][1], swz8(sB, row, ch));
            }
#pragma unroll
            for (int mt = 0; mt < 4; mt++)
#pragma unroll
                for (int nt = 0; nt < 8; nt++)
                    mma16816(acc[mt][nt], a4[mt], b4[nt]);
        }
    }
    __syncthreads();
}

// fused QKV: z=0 -> Q (scaled); z=1 -> K; z=2 -> V
__global__ __launch_bounds__(128, 2) void gemm_qkv(
    const __half* __restrict__ Xf, const __half* __restrict__ Wq,
    const __half* __restrict__ Wk, const __half* __restrict__ Wv,
    __half* __restrict__ Qf, __half* __restrict__ Kf, __half* __restrict__ Vf) {
    extern __shared__ char sm[];
    const uint32_t sb = smem_u32(sm);
    const int tid = threadIdx.x;
    const int lane = tid & 31;
    const int wid = tid >> 5;
    const int z = blockIdx.z;
    const int bm = blockIdx.y * BM;
    const int bn = blockIdx.x * BN;

    const __half* Bf = (z == 0) ? Wq : (z == 1) ? Wk : Wv;

    float acc[4][8][4];
    gemm_core1(sb, Xf, Bf, bm, bn, tid, acc);

    const int wm = wid & 1;
    const int wn = wid >> 1;
    __half* Dst = (z == 0) ? Qf : (z == 1) ? Kf : Vf;
    const float s = (z == 0) ? (QK_SCALE * INV_WSCALE) : INV_WSCALE;
#pragma unroll
    for (int mt = 0; mt < 4; mt++) {
        const int row = bm + wm * 64 + mt * 16 + (lane >> 2);
#pragma unroll
        for (int nt = 0; nt < 8; nt++) {
            const int col = bn + wn * 64 + nt * 8 + (lane & 3) * 2;
            *reinterpret_cast<uint32_t*>(&Dst[(size_t)row * D_EMB + col]) =
                pack_f16(acc[mt][nt][0] * s, acc[mt][nt][1] * s);
            *reinterpret_cast<uint32_t*>(&Dst[(size_t)(row + 8) * D_EMB + col]) =
                pack_f16(acc[mt][nt][2] * s, acc[mt][nt][3] * s);
        }
    }
}

// out-projection: fp32 output
__global__ __launch_bounds__(128, 2) void gemm_out(
    const __half* __restrict__ Af, const __half* __restrict__ Bf,
    float* __restrict__ C) {
    extern __shared__ char sm[];
    const uint32_t sb = smem_u32(sm);
    const int tid = threadIdx.x;
    const int lane = tid & 31;
    const int wid = tid >> 5;
    const int bm = blockIdx.y * BM;
    const int bn = blockIdx.x * BN;

    float acc[4][8][4];
    gemm_core1(sb, Af, Bf, bm, bn, tid, acc);

    const int wm = wid & 1;
    const int wn = wid >> 1;
#pragma unroll
    for (int mt = 0; mt < 4; mt++) {
        const int row = bm + wm * 64 + mt * 16 + (lane >> 2);
#pragma unroll
        for (int nt = 0; nt < 8; nt++) {
            const int col = bn + wn * 64 + nt * 8 + (lane & 3) * 2;
            *reinterpret_cast<float2*>(&C[(size_t)row * D_EMB + col]) =
                make_float2(acc[mt][nt][0] * INV_WSCALE, acc[mt][nt][1] * INV_WSCALE);
            *reinterpret_cast<float2*>(&C[(size_t)(row + 8) * D_EMB + col]) =
                make_float2(acc[mt][nt][2] * INV_WSCALE, acc[mt][nt][3] * INV_WSCALE);
        }
    }
}

// ---------------- fp16 HMMA flash attention (sequential-mt S) ----------------
#define ATTN_SMEM 65536

__global__ __launch_bounds__(128, 2) void attn_mma(
    const __half* __restrict__ Qf, const __half* __restrict__ Kf,
    const __half* __restrict__ Vf, __half* __restrict__ Rf) {
    extern __shared__ char sm[];
    const uint32_t sb = smem_u32(sm);
    const uint32_t sQ = sb;
    const uint32_t sK = sb + 32768;
    const uint32_t sV = sb + 49152;

    const int n = blockIdx.y;
    const int m0 = blockIdx.x * 128;
    const int tid = threadIdx.x;
    const int lane = tid & 31;
    const int w = tid >> 5;
    const int lr = lane & 7;
    const int lg = lane >> 3;

    // group 1: Q (128 rows x 256B)
    for (int u = tid; u < 2048; u += 128) {
        const int row = u >> 4, ch = u & 15;
        const uint32_t d = (uint32_t)((row * 16 + (ch ^ (row & 7))) * 16);
        CP_ASYNC16(sQ + d, Qf + (size_t)(m0 + row) * D_EMB + n * HD + ch * 8);
    }
    CP_COMMIT();
    // group 2: K(0)
    for (int u = tid; u < 1024; u += 128) {
        const int row = u >> 4, ch = u & 15;
        const uint32_t d = (uint32_t)((row * 16 + (ch ^ (row & 7))) * 16);
        CP_ASYNC16(sK + d, Kf + (size_t)row * D_EMB + n * HD + ch * 8);
    }
    CP_COMMIT();
    // group 3: V(0)
    for (int u = tid; u < 1024; u += 128) {
        const int row = u >> 4, ch = u & 15;
        const uint32_t d = (uint32_t)((row * 16 + (ch ^ (row & 7))) * 16);
        CP_ASYNC16(sV + d, Vf + (size_t)row * D_EMB + n * HD + ch * 8);
    }
    CP_COMMIT();

    float acc[2][16][4];
#pragma unroll
    for (int mt = 0; mt < 2; mt++)
#pragma unroll
        for (int ht = 0; ht < 16; ht++)
#pragma unroll
            for (int e = 0; e < 4; e++) acc[mt][ht][e] = 0.0f;
    float M0[2] = {-1e30f, -1e30f}, M1[2] = {-1e30f, -1e30f};
    float L0[2] = {0.0f, 0.0f}, L1[2] = {0.0f, 0.0f};

    const int NT = T_SEQ / 64;
    for (int it = 0; it < NT; it++) {
        CP_WAIT(1);
        __syncthreads();

        // ---- per m-tile: S, softmax, pack (c released before next mt) ----
        uint32_t P[2][4][4];
#pragma unroll
        for (int mt = 0; mt < 2; mt++) {
            float c[8][4];
#pragma unroll
            for (int t = 0; t < 8; t++)
#pragma unroll
                for (int e = 0; e < 4; e++) c[t][e] = 0.0f;

#pragma unroll
            for (int kk = 0; kk < 8; kk++) {
                uint32_t q4[4];
                {
                    const int row = w * 32 + mt * 16 + lr + (lg & 1) * 8;
                    const int ch = kk * 2 + (lg >> 1);
                    const uint32_t a =
                        (uint32_t)((row * 16 + (ch ^ (row & 7))) * 16);
                    ldsm_x4(q4[0], q4[1], q4[2], q4[3], sQ + a);
                }
#pragma unroll
                for (int np = 0; np < 4; np++) {
                    uint32_t k4[4];
                    const int row = np * 16 + lr + (lg >> 1) * 8;
                    const int ch = kk * 2 + (lg & 1);
                    const uint32_t a =
                        (uint32_t)((row * 16 + (ch ^ (row & 7))) * 16);
                    ldsm_x4(k4[0], k4[1], k4[2], k4[3], sK + a);
                    mma16816(c[np * 2],     q4, &k4[0]);
                    mma16816(c[np * 2 + 1], q4, &k4[2]);
                }
            }

            // online softmax for this m-tile
            float mx0 = -1e30f, mx1 = -1e30f;
#pragma unroll
            for (int t = 0; t < 8; t++) {
                mx0 = fmaxf(mx0, fmaxf(c[t][0], c[t][1]));
                mx1 = fmaxf(mx1, fmaxf(c[t][2], c[t][3]));
            }
            mx0 = fmaxf(mx0, __shfl_xor_sync(0xffffffffu, mx0, 1));
            mx0 = fmaxf(mx0, __shfl_xor_sync(0xffffffffu, mx0, 2));
            mx1 = fmaxf(mx1, __shfl_xor_sync(0xffffffffu, mx1, 1));
            mx1 = fmaxf(mx1, __shfl_xor_sync(0xffffffffu, mx1, 2));

            const float Mn0 = fmaxf(M0[mt], mx0), Mn1 = fmaxf(M1[mt], mx1);
            const float a0 = __expf(M0[mt] - Mn0), a1 = __expf(M1[mt] - Mn1);
            float sum0 = 0.0f, sum1 = 0.0f;
#pragma unroll
            for (int t = 0; t < 8; t++) {
                c[t][0] = __expf(c[t][0] - Mn0);
                c[t][1] = __expf(c[t][1] - Mn0);
                c[t][2] = __expf(c[t][2] - Mn1);
                c[t][3] = __expf(c[t][3] - Mn1);
                sum0 += c[t][0] + c[t][1];
                sum1 += c[t][2] + c[t][3];
            }
#pragma unroll
            for (int kk = 0; kk < 4; kk++) {
                P[mt][kk][0] = pack_f16(c[kk * 2][0], c[kk * 2][1]);
                P[mt][kk][1] = pack_f16(c[kk * 2][2], c[kk * 2][3]);
                P[mt][kk][2] = pack_f16(c[kk * 2 + 1][0], c[kk * 2 + 1][1]);
                P[mt][kk][3] = pack_f16(c[kk * 2 + 1][2], c[kk * 2 + 1][3]);
            }
            sum0 += __shfl_xor_sync(0xffffffffu, sum0, 1);
            sum0 += __shfl_xor_sync(0xffffffffu, sum0, 2);
            sum1 += __shfl_xor_sync(0xffffffffu, sum1, 1);
            sum1 += __shfl_xor_sync(0xffffffffu, sum1, 2);
            L0[mt] = L0[mt] * a0 + sum0;
            L1[mt] = L1[mt] * a1 + sum1;
            M0[mt] = Mn0;
            M1[mt] = Mn1;
#pragma unroll
            for (int ht = 0; ht < 16; ht++) {
                acc[mt][ht][0] *= a0;
                acc[mt][ht][1] *= a0;
                acc[mt][ht][2] *= a1;
                acc[mt][ht][3] *= a1;
            }
        }
        __syncthreads();  // all warps done reading K tile

        // prefetch K(it+1)
        if (it + 1 < NT) {
            for (int u = tid; u < 1024; u += 128) {
                const int row = u >> 4, ch = u & 15;
                const uint32_t d = (uint32_t)((row * 16 + (ch ^ (row & 7))) * 16);
                CP_ASYNC16(sK + d, Kf + (size_t)((it + 1) * 64 + row) * D_EMB +
                                       n * HD + ch * 8);
            }
            CP_COMMIT();
        }

        // V(it) ready
        if (it + 1 < NT) {
            CP_WAIT(1);
        } else {
            CP_WAIT(0);
        }
        __syncthreads();

        // ---- O += P V ----
#pragma unroll
        for (int kk = 0; kk < 4; kk++) {
#pragma unroll
            for (int hq = 0; hq < 8; hq++) {
                uint32_t v4[4];
                const int row = kk * 16 + (lg & 1) * 8 + lr;
                const int ch = hq * 2 + (lg >> 1);
                const uint32_t a = (uint32_t)((row * 16 + (ch ^ (row & 7))) * 16);
                ldsm_x4_t(v4[0], v4[1], v4[2], v4[3], sV + a);
#pragma unroll
                for (int mt = 0; mt < 2; mt++) {
                    mma16816(acc[mt][hq * 2],     P[mt][kk], &v4[0]);
                    mma16816(acc[mt][hq * 2 + 1], P[mt][kk], &v4[2]);
                }
            }
        }
        __syncthreads();

        // prefetch V(it+1)
        if (it + 1 < NT) {
            for (int u = tid; u < 1024; u += 128) {
                const int row = u >> 4, ch = u & 15;
                const uint32_t d = (uint32_t)((row * 16 + (ch ^ (row & 7))) * 16);
                CP_ASYNC16(sV + d, Vf + (size_t)((it + 1) * 64 + row) * D_EMB +
                                       n * HD + ch * 8);
            }
            CP_COMMIT();
        }
    }

#pragma unroll
    for (int mt = 0; mt < 2; mt++) {
        const float i0 = 1.0f / L0[mt], i1 = 1.0f / L1[mt];
        const int rowg = m0 + w * 32 + mt * 16 + (lane >> 2);
#pragma unroll
        for (int ht = 0; ht < 16; ht++) {
            const int col = n * HD + ht * 8 + (lane & 3) * 2;
            *reinterpret_cast<uint32_t*>(&Rf[(size_t)rowg * D_EMB + col]) =
                pack_f16(acc[mt][ht][0] * i0, acc[mt][ht][1] * i0);
            *reinterpret_cast<uint32_t*>(&Rf[(size_t)(rowg + 8) * D_EMB + col]) =
                pack_f16(acc[mt][ht][2] * i1, acc[mt][ht][3] * i1);
        }
    }
}

// ---------------------------------------------------------------------------
extern "C" void kernel_launch(void* const* d_in, const int* in_sizes, int n_in,
                              void* d_out, int out_size) {
    const float* X  = (const float*)d_in[0];
    const float* Wq = (const float*)d_in[1];
    const float* Wk = (const float*)d_in[2];
    const float* Wv = (const float*)d_in[3];
    const float* Wo = (const float*)d_in[4];
    float* out = (float*)d_out;

    __half *xf, *rf, *qf, *kf, *vf, *wq, *wk, *wv, *wo;
    cudaGetSymbolAddress((void**)&xf, g_Xf);
    cudaGetSymbolAddress((void**)&rf, g_Rf);
    cudaGetSymbolAddress((void**)&qf, g_Qf);
    cudaGetSymbolAddress((void**)&kf, g_Kf);
    cudaGetSymbolAddress((void**)&vf, g_Vf);
    cudaGetSymbolAddress((void**)&wq, g_Wq);
    cudaGetSymbolAddress((void**)&wk, g_Wk);
    cudaGetSymbolAddress((void**)&wv, g_Wv);
    cudaGetSymbolAddress((void**)&wo, g_Wo);

    const int NELE4 = T_SEQ * D_EMB / 4 / 256;

    convX<<<NELE4, 256>>>(X, xf);
    convW16all<<<dim3(64, 64, 4), dim3(32, 8)>>>(Wq, Wk, Wv, Wo, wq, wk, wv, wo);

    cudaFuncSetAttribute(gemm_qkv, cudaFuncAttributeMaxDynamicSharedMemorySize,
                         GEMM_SMEM);
    cudaFuncSetAttribute(gemm_out, cudaFuncAttributeMaxDynamicSharedMemorySize,
                         GEMM_SMEM);
    gemm_qkv<<<dim3(D_EMB / BN, T_SEQ / BM, 3), 128, GEMM_SMEM>>>(xf, wq, wk, wv,
                                                                  qf, kf, vf);

    cudaFuncSetAttribute(attn_mma, cudaFuncAttributeMaxDynamicSharedMemorySize,
                         ATTN_SMEM);
    attn_mma<<<dim3(T_SEQ / 128, NHEADS), 128, ATTN_SMEM>>>(qf, kf, vf, rf);

    gemm_out<<<dim3(D_EMB / BN, T_SEQ / BM), 128, GEMM_SMEM>>>(rf, wo, out);
}

// round 12
// speedup vs baseline: 1.0121x; 1.0121x over previous
#include <cuda_runtime.h>
#include <cuda_fp16.h>
#include <stdint.h>
#include <math.h>

#define T_SEQ 2048
#define D_EMB 2048
#define HD    128
#define NHEADS 16
#define QK_SCALE 0.08838834764831843f
#define WSCALE 256.0f
#define INV_WSCALE (1.0f / 256.0f)

// ---------------- scratch (no allocs allowed) ----------------
__device__ __half g_Xf[T_SEQ * D_EMB];
__device__ __half g_Rf[T_SEQ * D_EMB];
__device__ __half g_Wq[D_EMB * D_EMB];
__device__ __half g_Wk[D_EMB * D_EMB];
__device__ __half g_Wv[D_EMB * D_EMB];
__device__ __half g_Wo[D_EMB * D_EMB];
__device__ __half g_Qf[T_SEQ * D_EMB];
__device__ __half g_Kf[T_SEQ * D_EMB];
__device__ __half g_Vf[T_SEQ * D_EMB];

// ---------------- PTX helpers (base sm_103-legal only) ----------------
__device__ __forceinline__ uint32_t smem_u32(const void* p) {
    uint32_t a;
    asm("{ .reg .u64 t; cvta.to.shared.u64 t, %1; cvt.u32.u64 %0, t; }"
        : "=r"(a) : "l"(p));
    return a;
}
#define CP_ASYNC16(dst, src) \
    asm volatile("cp.async.cg.shared.global [%0], [%1], 16;" :: "r"(dst), "l"(src))
#define CP_COMMIT() asm volatile("cp.async.commit_group;" ::: "memory")
#define CP_WAIT(n) asm volatile("cp.async.wait_group %0;" :: "n"(n) : "memory")

__device__ __forceinline__ void ldsm_x4(uint32_t& r0, uint32_t& r1, uint32_t& r2,
                                        uint32_t& r3, uint32_t addr) {
    asm volatile("ldmatrix.sync.aligned.m8n8.x4.shared.b16 {%0,%1,%2,%3}, [%4];"
                 : "=r"(r0), "=r"(r1), "=r"(r2), "=r"(r3) : "r"(addr));
}
__device__ __forceinline__ void ldsm_x4_t(uint32_t& r0, uint32_t& r1, uint32_t& r2,
                                          uint32_t& r3, uint32_t addr) {
    asm volatile(
        "ldmatrix.sync.aligned.m8n8.x4.trans.shared.b16 {%0,%1,%2,%3}, [%4];"
        : "=r"(r0), "=r"(r1), "=r"(r2), "=r"(r3) : "r"(addr));
}
__device__ __forceinline__ void mma16816(float* c, const uint32_t* a,
                                         const uint32_t* b) {
    asm volatile(
        "mma.sync.aligned.m16n8k16.row.col.f32.f16.f16.f32 "
        "{%0,%1,%2,%3}, {%4,%5,%6,%7}, {%8,%9}, {%0,%1,%2,%3};"
        : "+f"(c[0]), "+f"(c[1]), "+f"(c[2]), "+f"(c[3])
        : "r"(a[0]), "r"(a[1]), "r"(a[2]), "r"(a[3]), "r"(b[0]), "r"(b[1]));
}
__device__ __forceinline__ uint32_t pack_f16(float x, float y) {
    __half2 h = __floats2half2_rn(x, y);
    return *reinterpret_cast<uint32_t*>(&h);
}

// ---------------- conversion kernels ----------------
__global__ __launch_bounds__(256) void convX(const float* __restrict__ A,
                                             __half* __restrict__ F) {
    const int i = blockIdx.x * 256 + threadIdx.x;
    float4 v = reinterpret_cast<const float4*>(A)[i];
    __half f[4] = {__float2half_rn(v.x), __float2half_rn(v.y),
                   __float2half_rn(v.z), __float2half_rn(v.w)};
    reinterpret_cast<uint2*>(F)[i] = *reinterpret_cast<uint2*>(f);
}

// merged weight conversion, k-tile 64 + half2 writes (128B coalesced stores)
__global__ __launch_bounds__(256) void convW16all(
    const float* __restrict__ Wq, const float* __restrict__ Wk,
    const float* __restrict__ Wv, const float* __restrict__ Wo,
    __half* __restrict__ Hq, __half* __restrict__ Hk,
    __half* __restrict__ Hv, __half* __restrict__ Ho) {
    __shared__ float t[64][33];
    const int z = blockIdx.z;
    const float* W = (z == 0) ? Wq : (z == 1) ? Wk : (z == 2) ? Wv : Wo;
    __half* H = (z == 0) ? Hq : (z == 1) ? Hk : (z == 2) ? Hv : Ho;
    const int hd = (z == 3) ? D_EMB : HD;
    const int n  = (z == 3) ? 0 : ((int)blockIdx.x >> 2);
    const int j0 = (z == 3) ? ((int)blockIdx.x * 32) : (((int)blockIdx.x & 3) * 32);
    const int k0 = blockIdx.y * 64;
    const int tx = threadIdx.x, ty = threadIdx.y;
    const float* Wn = W + (size_t)n * D_EMB * hd;
#pragma unroll
    for (int y = ty; y < 64; y += 8) t[y][tx] = Wn[(size_t)(k0 + y) * hd + j0 + tx];
    __syncthreads();
#pragma unroll
    for (int y = ty; y < 32; y += 8) {
        const float a = t[2 * tx][y] * WSCALE;
        const float b = t[2 * tx + 1][y] * WSCALE;
        *reinterpret_cast<uint32_t*>(
            &H[(size_t)(n * hd + j0 + y) * D_EMB + k0 + 2 * tx]) = pack_f16(a, b);
    }
}

// ---------------- 1-pass fp16 HMMA GEMM (CTA 256x128, warp 64x64) ----------------
#define BM 256
#define BN 128
#define BK 64
#define STAGE_B 49152   // A 32K + B 16K
#define GEMM_SMEM (3 * STAGE_B)

__device__ __forceinline__ uint32_t swz8(uint32_t base, int row, int chunk) {
    return base + (((row << 3) + (chunk ^ (row & 7))) << 4);
}

__device__ __forceinline__ void stage_all(uint32_t sbase, const __half* Af,
                                          const __half* Bf, int bm, int bn,
                                          int k0, int tid) {
    // A: 256 rows x 64 cols = 2048 16B chunks
#pragma unroll
    for (int u = tid; u < 2048; u += 256) {
        const int row = u >> 3, ch = u & 7;
        CP_ASYNC16(swz8(sbase, row, ch),
                   Af + (size_t)(bm + row) * D_EMB + k0 + ch * 8);
    }
    // B: 128 rows x 64 cols = 1024 chunks
#pragma unroll
    for (int u = tid; u < 1024; u += 256) {
        const int row = u >> 3, ch = u & 7;
        CP_ASYNC16(swz8(sbase + 32768, row, ch),
                   Bf + (size_t)(bn + row) * D_EMB + k0 + ch * 8);
    }
    CP_COMMIT();
}

__device__ __forceinline__ void gemm_core1(
    uint32_t sb, const __half* Af, const __half* Bf, int bm, int bn, int tid,
    float acc[4][8][4]) {
    const int lane = tid & 31;
    const int wid = tid >> 5;
    const int wm = wid & 3;   // 4m x 2n warp grid
    const int wn = wid >> 2;
    const int lr = lane & 7;
    const int lg = lane >> 3;

#pragma unroll
    for (int mt = 0; mt < 4; mt++)
#pragma unroll
        for (int nt = 0; nt < 8; nt++)
#pragma unroll
            for (int e = 0; e < 4; e++) acc[mt][nt][e] = 0.0f;

    stage_all(sb + 0 * STAGE_B, Af, Bf, bm, bn, 0, tid);
    stage_all(sb + 1 * STAGE_B, Af, Bf, bm, bn, BK, tid);

    const int NITER = D_EMB / BK;  // 32
    for (int c = 0; c < NITER; c++) {
        if (c == NITER - 1) {
            CP_WAIT(0);
        } else {
            CP_WAIT(1);
        }
        __syncthreads();
        if (c + 2 < NITER)
            stage_all(sb + ((c + 2) % 3) * STAGE_B, Af, Bf, bm, bn,
                      (c + 2) * BK, tid);

        const uint32_t sX = sb + (c % 3) * STAGE_B;
        const uint32_t sB = sX + 32768;

#pragma unroll
        for (int kk = 0; kk < 4; kk++) {
            uint32_t a4[4][4];
#pragma unroll
            for (int mt = 0; mt < 4; mt++) {
                const int row = wm * 64 + mt * 16 + lr + (lg & 1) * 8;
                const int ch = kk * 2 + (lg >> 1);
                ldsm_x4(a4[mt][0], a4[mt][1], a4[mt][2], a4[mt][3],
                        swz8(sX, row, ch));
            }
            uint32_t b4[8][2];
#pragma unroll
            for (int np = 0; np < 4; np++) {
                const int row = wn * 64 + np * 16 + lr + (lg >> 1) * 8;
                const int ch = kk * 2 + (lg & 1);
                ldsm_x4(b4[np * 2][0], b4[np * 2][1], b4[np * 2 + 1][0],
                        b4[np * 2 + 1][1], swz8(sB, row, ch));
            }
#pragma unroll
            for (int mt = 0; mt < 4; mt++)
#pragma unroll
                for (int nt = 0; nt < 8; nt++)
                    mma16816(acc[mt][nt], a4[mt], b4[nt]);
        }
    }
    __syncthreads();
}

// fused QKV: z=0 -> Q (scaled); z=1 -> K; z=2 -> V
__global__ __launch_bounds__(256, 1) void gemm_qkv(
    const __half* __restrict__ Xf, const __half* __restrict__ Wq,
    const __half* __restrict__ Wk, const __half* __restrict__ Wv,
    __half* __restrict__ Qf, __half* __restrict__ Kf, __half* __restrict__ Vf) {
    extern __shared__ char sm[];
    const uint32_t sb = smem_u32(sm);
    const int tid = threadIdx.x;
    const int lane = tid & 31;
    const int wid = tid >> 5;
    const int z = blockIdx.z;
    const int bm = blockIdx.y * BM;
    const int bn = blockIdx.x * BN;

    const __half* Bf = (z == 0) ? Wq : (z == 1) ? Wk : Wv;

    float acc[4][8][4];
    gemm_core1(sb, Xf, Bf, bm, bn, tid, acc);

    const int wm = wid & 3;
    const int wn = wid >> 2;
    __half* Dst = (z == 0) ? Qf : (z == 1) ? Kf : Vf;
    const float s = (z == 0) ? (QK_SCALE * INV_WSCALE) : INV_WSCALE;
#pragma unroll
    for (int mt = 0; mt < 4; mt++) {
        const int row = bm + wm * 64 + mt * 16 + (lane >> 2);
#pragma unroll
        for (int nt = 0; nt < 8; nt++) {
            const int col = bn + wn * 64 + nt * 8 + (lane & 3) * 2;
            *reinterpret_cast<uint32_t*>(&Dst[(size_t)row * D_EMB + col]) =
                pack_f16(acc[mt][nt][0] * s, acc[mt][nt][1] * s);
            *reinterpret_cast<uint32_t*>(&Dst[(size_t)(row + 8) * D_EMB + col]) =
                pack_f16(acc[mt][nt][2] * s, acc[mt][nt][3] * s);
        }
    }
}

// out-projection: fp32 output
__global__ __launch_bounds__(256, 1) void gemm_out(
    const __half* __restrict__ Af, const __half* __restrict__ Bf,
    float* __restrict__ C) {
    extern __shared__ char sm[];
    const uint32_t sb = smem_u32(sm);
    const int tid = threadIdx.x;
    const int lane = tid & 31;
    const int wid = tid >> 5;
    const int bm = blockIdx.y * BM;
    const int bn = blockIdx.x * BN;

    float acc[4][8][4];
    gemm_core1(sb, Af, Bf, bm, bn, tid, acc);

    const int wm = wid & 3;
    const int wn = wid >> 2;
#pragma unroll
    for (int mt = 0; mt < 4; mt++) {
        const int row = bm + wm * 64 + mt * 16 + (lane >> 2);
#pragma unroll
        for (int nt = 0; nt < 8; nt++) {
            const int col = bn + wn * 64 + nt * 8 + (lane & 3) * 2;
            *reinterpret_cast<float2*>(&C[(size_t)row * D_EMB + col]) =
                make_float2(acc[mt][nt][0] * INV_WSCALE, acc[mt][nt][1] * INV_WSCALE);
            *reinterpret_cast<float2*>(&C[(size_t)(row + 8) * D_EMB + col]) =
                make_float2(acc[mt][nt][2] * INV_WSCALE, acc[mt][nt][3] * INV_WSCALE);
        }
    }
}

// ---------------- fp16 HMMA flash attention (round-9 config) ----------------
#define ATTN_SMEM 65536

__global__ __launch_bounds__(128, 2) void attn_mma(
    const __half* __restrict__ Qf, const __half* __restrict__ Kf,
    const __half* __restrict__ Vf, __half* __restrict__ Rf) {
    extern __shared__ char sm[];
    const uint32_t sb = smem_u32(sm);
    const uint32_t sQ = sb;
    const uint32_t sK = sb + 32768;
    const uint32_t sV = sb + 49152;

    const int n = blockIdx.y;
    const int m0 = blockIdx.x * 128;
    const int tid = threadIdx.x;
    const int lane = tid & 31;
    const int w = tid >> 5;
    const int lr = lane & 7;
    const int lg = lane >> 3;

    // group 1: Q (128 rows x 256B)
    for (int u = tid; u < 2048; u += 128) {
        const int row = u >> 4, ch = u & 15;
        const uint32_t d = (uint32_t)((row * 16 + (ch ^ (row & 7))) * 16);
        CP_ASYNC16(sQ + d, Qf + (size_t)(m0 + row) * D_EMB + n * HD + ch * 8);
    }
    CP_COMMIT();
    // group 2: K(0)
    for (int u = tid; u < 1024; u += 128) {
        const int row = u >> 4, ch = u & 15;
        const uint32_t d = (uint32_t)((row * 16 + (ch ^ (row & 7))) * 16);
        CP_ASYNC16(sK + d, Kf + (size_t)row * D_EMB + n * HD + ch * 8);
    }
    CP_COMMIT();
    // group 3: V(0)
    for (int u = tid; u < 1024; u += 128) {
        const int row = u >> 4, ch = u & 15;
        const uint32_t d = (uint32_t)((row * 16 + (ch ^ (row & 7))) * 16);
        CP_ASYNC16(sV + d, Vf + (size_t)row * D_EMB + n * HD + ch * 8);
    }
    CP_COMMIT();

    float acc[2][16][4];
#pragma unroll
    for (int mt = 0; mt < 2; mt++)
#pragma unroll
        for (int ht = 0; ht < 16; ht++)
#pragma unroll
            for (int e = 0; e < 4; e++) acc[mt][ht][e] = 0.0f;
    float M0[2] = {-1e30f, -1e30f}, M1[2] = {-1e30f, -1e30f};
    float L0[2] = {0.0f, 0.0f}, L1[2] = {0.0f, 0.0f};

    const int NT = T_SEQ / 64;
    for (int it = 0; it < NT; it++) {
        CP_WAIT(1);
        __syncthreads();

        // ---- S = Q K^T for 2 m-tiles ----
        float c[2][8][4];
#pragma unroll
        for (int mt = 0; mt < 2; mt++)
#pragma unroll
            for (int t = 0; t < 8; t++)
#pragma unroll
                for (int e = 0; e < 4; e++) c[mt][t][e] = 0.0f;

#pragma unroll
        for (int kk = 0; kk < 8; kk++) {
            uint32_t q4[2][4];
#pragma unroll
            for (int mt = 0; mt < 2; mt++) {
                const int row = w * 32 + mt * 16 + lr + (lg & 1) * 8;
                const int ch = kk * 2 + (lg >> 1);
                const uint32_t a = (uint32_t)((row * 16 + (ch ^ (row & 7))) * 16);
                ldsm_x4(q4[mt][0], q4[mt][1], q4[mt][2], q4[mt][3], sQ + a);
            }
#pragma unroll
            for (int np = 0; np < 4; np++) {
                uint32_t k4[4];
                const int row = np * 16 + lr + (lg >> 1) * 8;
                const int ch = kk * 2 + (lg & 1);
                const uint32_t a = (uint32_t)((row * 16 + (ch ^ (row & 7))) * 16);
                ldsm_x4(k4[0], k4[1], k4[2], k4[3], sK + a);
#pragma unroll
                for (int mt = 0; mt < 2; mt++) {
                    mma16816(c[mt][np * 2],     q4[mt], &k4[0]);
                    mma16816(c[mt][np * 2 + 1], q4[mt], &k4[2]);
                }
            }
        }
        __syncthreads();

        // prefetch K(it+1)
        if (it + 1 < NT) {
            for (int u = tid; u < 1024; u += 128) {
                const int row = u >> 4, ch = u & 15;
                const uint32_t d = (uint32_t)((row * 16 + (ch ^ (row & 7))) * 16);
                CP_ASYNC16(sK + d, Kf + (size_t)((it + 1) * 64 + row) * D_EMB +
                                       n * HD + ch * 8);
            }
            CP_COMMIT();
        }

        // ---- online softmax ----
#pragma unroll
        for (int mt = 0; mt < 2; mt++) {
            float mx0 = -1e30f, mx1 = -1e30f;
#pragma unroll
            for (int t = 0; t < 8; t++) {
                mx0 = fmaxf(mx0, fmaxf(c[mt][t][0], c[mt][t][1]));
                mx1 = fmaxf(mx1, fmaxf(c[mt][t][2], c[mt][t][3]));
            }
            mx0 = fmaxf(mx0, __shfl_xor_sync(0xffffffffu, mx0, 1));
            mx0 = fmaxf(mx0, __shfl_xor_sync(0xffffffffu, mx0, 2));
            mx1 = fmaxf(mx1, __shfl_xor_sync(0xffffffffu, mx1, 1));
            mx1 = fmaxf(mx1, __shfl_xor_sync(0xffffffffu, mx1, 2));

            const float Mn0 = fmaxf(M0[mt], mx0), Mn1 = fmaxf(M1[mt], mx1);
            const float a0 = __expf(M0[mt] - Mn0), a1 = __expf(M1[mt] - Mn1);
            float sum0 = 0.0f, sum1 = 0.0f;
#pragma unroll
            for (int t = 0; t < 8; t++) {
                c[mt][t][0] = __expf(c[mt][t][0] - Mn0);
                c[mt][t][1] = __expf(c[mt][t][1] - Mn0);
                c[mt][t][2] = __expf(c[mt][t][2] - Mn1);
                c[mt][t][3] = __expf(c[mt][t][3] - Mn1);
                sum0 += c[mt][t][0] + c[mt][t][1];
                sum1 += c[mt][t][2] + c[mt][t][3];
            }
            sum0 += __shfl_xor_sync(0xffffffffu, sum0, 1);
            sum0 += __shfl_xor_sync(0xffffffffu, sum0, 2);
            sum1 += __shfl_xor_sync(0xffffffffu, sum1, 1);
            sum1 += __shfl_xor_sync(0xffffffffu, sum1, 2);
            L0[mt] = L0[mt] * a0 + sum0;
            L1[mt] = L1[mt] * a1 + sum1;
            M0[mt] = Mn0;
            M1[mt] = Mn1;
#pragma unroll
            for (int ht = 0; ht < 16; ht++) {
                acc[mt][ht][0] *= a0;
                acc[mt][ht][1] *= a0;
                acc[mt][ht][2] *= a1;
                acc[mt][ht][3] *= a1;
            }
        }

        // V(it) ready
        if (it + 1 < NT) {
            CP_WAIT(1);
        } else {
            CP_WAIT(0);
        }
        __syncthreads();

        // ---- O += P V (pack at use) ----
#pragma unroll
        for (int kk = 0; kk < 4; kk++) {
            uint32_t ap[2][4];
#pragma unroll
            for (int mt = 0; mt < 2; mt++) {
                const int t0 = kk * 2, t1 = kk * 2 + 1;
                ap[mt][0] = pack_f16(c[mt][t0][0], c[mt][t0][1]);
                ap[mt][1] = pack_f16(c[mt][t0][2], c[mt][t0][3]);
                ap[mt][2] = pack_f16(c[mt][t1][0], c[mt][t1][1]);
                ap[mt][3] = pack_f16(c[mt][t1][2], c[mt][t1][3]);
            }
#pragma unroll
            for (int hq = 0; hq < 8; hq++) {
                uint32_t v4[4];
                const int row = kk * 16 + (lg & 1) * 8 + lr;
                const int ch = hq * 2 + (lg >> 1);
                const uint32_t a = (uint32_t)((row * 16 + (ch ^ (row & 7))) * 16);
                ldsm_x4_t(v4[0], v4[1], v4[2], v4[3], sV + a);
#pragma unroll
                for (int mt = 0; mt < 2; mt++) {
                    mma16816(acc[mt][hq * 2],     ap[mt], &v4[0]);
                    mma16816(acc[mt][hq * 2 + 1], ap[mt], &v4[2]);
                }
            }
        }
        __syncthreads();

        // prefetch V(it+1)
        if (it + 1 < NT) {
            for (int u = tid; u < 1024; u += 128) {
                const int row = u >> 4, ch = u & 15;
                const uint32_t d = (uint32_t)((row * 16 + (ch ^ (row & 7))) * 16);
                CP_ASYNC16(sV + d, Vf + (size_t)((it + 1) * 64 + row) * D_EMB +
                                       n * HD + ch * 8);
            }
            CP_COMMIT();
        }
    }

#pragma unroll
    for (int mt = 0; mt < 2; mt++) {
        const float i0 = 1.0f / L0[mt], i1 = 1.0f / L1[mt];
        const int rowg = m0 + w * 32 + mt * 16 + (lane >> 2);
#pragma unroll
        for (int ht = 0; ht < 16; ht++) {
            const int col = n * HD + ht * 8 + (lane & 3) * 2;
            *reinterpret_cast<uint32_t*>(&Rf[(size_t)rowg * D_EMB + col]) =
                pack_f16(acc[mt][ht][0] * i0, acc[mt][ht][1] * i0);
            *reinterpret_cast<uint32_t*>(&Rf[(size_t)(rowg + 8) * D_EMB + col]) =
                pack_f16(acc[mt][ht][2] * i1, acc[mt][ht][3] * i1);
        }
    }
}

// ---------------------------------------------------------------------------
extern "C" void kernel_launch(void* const* d_in, const int* in_sizes, int n_in,
                              void* d_out, int out_size) {
    const float* X  = (const float*)d_in[0];
    const float* Wq = (const float*)d_in[1];
    const float* Wk = (const float*)d_in[2];
    const float* Wv = (const float*)d_in[3];
    const float* Wo = (const float*)d_in[4];
    float* out = (float*)d_out;

    __half *xf, *rf, *qf, *kf, *vf, *wq, *wk, *wv, *wo;
    cudaGetSymbolAddress((void**)&xf, g_Xf);
    cudaGetSymbolAddress((void**)&rf, g_Rf);
    cudaGetSymbolAddress((void**)&qf, g_Qf);
    cudaGetSymbolAddress((void**)&kf, g_Kf);
    cudaGetSymbolAddress((void**)&vf, g_Vf);
    cudaGetSymbolAddress((void**)&wq, g_Wq);
    cudaGetSymbolAddress((void**)&wk, g_Wk);
    cudaGetSymbolAddress((void**)&wv, g_Wv);
    cudaGetSymbolAddress((void**)&wo, g_Wo);

    const int NELE4 = T_SEQ * D_EMB / 4 / 256;

    convX<<<NELE4, 256>>>(X, xf);
    convW16all<<<dim3(64, 32, 4), dim3(32, 8)>>>(Wq, Wk, Wv, Wo, wq, wk, wv, wo);

    cudaFuncSetAttribute(gemm_qkv, cudaFuncAttributeMaxDynamicSharedMemorySize,
                         GEMM_SMEM);
    cudaFuncSetAttribute(gemm_out, cudaFuncAttributeMaxDynamicSharedMemorySize,
                         GEMM_SMEM);
    gemm_qkv<<<dim3(D_EMB / BN, T_SEQ / BM, 3), 256, GEMM_SMEM>>>(xf, wq, wk, wv,
                                                                  qf, kf, vf);

    cudaFuncSetAttribute(attn_mma, cudaFuncAttributeMaxDynamicSharedMemorySize,
                         ATTN_SMEM);
    attn_mma<<<dim3(T_SEQ / 128, NHEADS), 128, ATTN_SMEM>>>(qf, kf, vf, rf);

    gemm_out<<<dim3(D_EMB / BN, T_SEQ / BM), 256, GEMM_SMEM>>>(rf, wo, out);
}

// round 13
// speedup vs baseline: 1.0612x; 1.0486x over previous
#include <cuda_runtime.h>
#include <cuda_fp16.h>
#include <stdint.h>
#include <math.h>

#define T_SEQ 2048
#define D_EMB 2048
#define HD    128
#define NHEADS 16
#define QK_SCALE 0.08838834764831843f
#define WSCALE 256.0f
#define INV_WSCALE (1.0f / 256.0f)

// ---------------- scratch (no allocs allowed) ----------------
__device__ __half g_Xf[T_SEQ * D_EMB];
__device__ __half g_Rf[T_SEQ * D_EMB];
__device__ __half g_Wq[D_EMB * D_EMB];
__device__ __half g_Wk[D_EMB * D_EMB];
__device__ __half g_Wv[D_EMB * D_EMB];
__device__ __half g_Wo[D_EMB * D_EMB];
__device__ __half g_Qf[T_SEQ * D_EMB];
__device__ __half g_Kf[T_SEQ * D_EMB];
__device__ __half g_Vf[T_SEQ * D_EMB];

// ---------------- PTX helpers (base sm_103-legal only) ----------------
__device__ __forceinline__ uint32_t smem_u32(const void* p) {
    uint32_t a;
    asm("{ .reg .u64 t; cvta.to.shared.u64 t, %1; cvt.u32.u64 %0, t; }"
        : "=r"(a) : "l"(p));
    return a;
}
#define CP_ASYNC16(dst, src) \
    asm volatile("cp.async.cg.shared.global [%0], [%1], 16;" :: "r"(dst), "l"(src))
#define CP_COMMIT() asm volatile("cp.async.commit_group;" ::: "memory")
#define CP_WAIT(n) asm volatile("cp.async.wait_group %0;" :: "n"(n) : "memory")

__device__ __forceinline__ void ldsm_x4(uint32_t& r0, uint32_t& r1, uint32_t& r2,
                                        uint32_t& r3, uint32_t addr) {
    asm volatile("ldmatrix.sync.aligned.m8n8.x4.shared.b16 {%0,%1,%2,%3}, [%4];"
                 : "=r"(r0), "=r"(r1), "=r"(r2), "=r"(r3) : "r"(addr));
}
__device__ __forceinline__ void ldsm_x4_t(uint32_t& r0, uint32_t& r1, uint32_t& r2,
                                          uint32_t& r3, uint32_t addr) {
    asm volatile(
        "ldmatrix.sync.aligned.m8n8.x4.trans.shared.b16 {%0,%1,%2,%3}, [%4];"
        : "=r"(r0), "=r"(r1), "=r"(r2), "=r"(r3) : "r"(addr));
}
__device__ __forceinline__ void mma16816(float* c, const uint32_t* a,
                                         const uint32_t* b) {
    asm volatile(
        "mma.sync.aligned.m16n8k16.row.col.f32.f16.f16.f32 "
        "{%0,%1,%2,%3}, {%4,%5,%6,%7}, {%8,%9}, {%0,%1,%2,%3};"
        : "+f"(c[0]), "+f"(c[1]), "+f"(c[2]), "+f"(c[3])
        : "r"(a[0]), "r"(a[1]), "r"(a[2]), "r"(a[3]), "r"(b[0]), "r"(b[1]));
}
__device__ __forceinline__ uint32_t pack_f16(float x, float y) {
    __half2 h = __floats2half2_rn(x, y);
    return *reinterpret_cast<uint32_t*>(&h);
}

// ---------------- conversion kernels ----------------
__global__ __launch_bounds__(256) void convX(const float* __restrict__ A,
                                             __half* __restrict__ F) {
    const int i = blockIdx.x * 256 + threadIdx.x;
    float4 v = reinterpret_cast<const float4*>(A)[i];
    __half f[4] = {__float2half_rn(v.x), __float2half_rn(v.y),
                   __float2half_rn(v.z), __float2half_rn(v.w)};
    reinterpret_cast<uint2*>(F)[i] = *reinterpret_cast<uint2*>(f);
}

// merged weight conversion, k-tile 64 + half2 writes (128B coalesced stores)
__global__ __launch_bounds__(256) void convW16all(
    const float* __restrict__ Wq, const float* __restrict__ Wk,
    const float* __restrict__ Wv, const float* __restrict__ Wo,
    __half* __restrict__ Hq, __half* __restrict__ Hk,
    __half* __restrict__ Hv, __half* __restrict__ Ho) {
    __shared__ float t[64][33];
    const int z = blockIdx.z;
    const float* W = (z == 0) ? Wq : (z == 1) ? Wk : (z == 2) ? Wv : Wo;
    __half* H = (z == 0) ? Hq : (z == 1) ? Hk : (z == 2) ? Hv : Ho;
    const int hd = (z == 3) ? D_EMB : HD;
    const int n  = (z == 3) ? 0 : ((int)blockIdx.x >> 2);
    const int j0 = (z == 3) ? ((int)blockIdx.x * 32) : (((int)blockIdx.x & 3) * 32);
    const int k0 = blockIdx.y * 64;
    const int tx = threadIdx.x, ty = threadIdx.y;
    const float* Wn = W + (size_t)n * D_EMB * hd;
#pragma unroll
    for (int y = ty; y < 64; y += 8) t[y][tx] = Wn[(size_t)(k0 + y) * hd + j0 + tx];
    __syncthreads();
#pragma unroll
    for (int y = ty; y < 32; y += 8) {
        const float a = t[2 * tx][y] * WSCALE;
        const float b = t[2 * tx + 1][y] * WSCALE;
        *reinterpret_cast<uint32_t*>(
            &H[(size_t)(n * hd + j0 + y) * D_EMB + k0 + 2 * tx]) = pack_f16(a, b);
    }
}

// ---------------- 1-pass fp16 HMMA GEMM (round-9 config: 128x128, BK=64) -----
#define BM 128
#define BN 128
#define BK 64
#define STAGE_B 32768
#define GEMM_SMEM (3 * STAGE_B)

__device__ __forceinline__ uint32_t swz8(uint32_t base, int row, int chunk) {
    return base + (((row << 3) + (chunk ^ (row & 7))) << 4);
}

__device__ __forceinline__ void stage_tile64(uint32_t sbase,
                                             const __half* __restrict__ g,
                                             int row0, int k0, int tid) {
#pragma unroll
    for (int u = tid; u < 1024; u += 128) {
        const int row = u >> 3, ch = u & 7;
        const uint32_t dst = swz8(sbase, row, ch);
        const __half* src = g + (size_t)(row0 + row) * D_EMB + k0 + ch * 8;
        CP_ASYNC16(dst, src);
    }
}

__device__ __forceinline__ void stage_all(uint32_t sbase, const __half* Af,
                                          const __half* Bf, int bm, int bn,
                                          int k0, int tid) {
    stage_tile64(sbase + 0,     Af, bm, k0, tid);
    stage_tile64(sbase + 16384, Bf, bn, k0, tid);
    CP_COMMIT();
}

__device__ __forceinline__ void gemm_core1(
    uint32_t sb, const __half* Af, const __half* Bf, int bm, int bn, int tid,
    float acc[4][8][4]) {
    const int lane = tid & 31;
    const int wid = tid >> 5;
    const int wm = wid & 1;
    const int wn = wid >> 1;
    const int lr = lane & 7;
    const int lg = lane >> 3;

#pragma unroll
    for (int mt = 0; mt < 4; mt++)
#pragma unroll
        for (int nt = 0; nt < 8; nt++)
#pragma unroll
            for (int e = 0; e < 4; e++) acc[mt][nt][e] = 0.0f;

    stage_all(sb + 0 * STAGE_B, Af, Bf, bm, bn, 0, tid);
    stage_all(sb + 1 * STAGE_B, Af, Bf, bm, bn, BK, tid);

    const int NITER = D_EMB / BK;  // 32
    for (int c = 0; c < NITER; c++) {
        if (c == NITER - 1) {
            CP_WAIT(0);
        } else {
            CP_WAIT(1);
        }
        __syncthreads();
        if (c + 2 < NITER)
            stage_all(sb + ((c + 2) % 3) * STAGE_B, Af, Bf, bm, bn,
                      (c + 2) * BK, tid);

        const uint32_t sX = sb + (c % 3) * STAGE_B;
        const uint32_t sB = sX + 16384;

#pragma unroll
        for (int kk = 0; kk < 4; kk++) {
            uint32_t a4[4][4];
#pragma unroll
            for (int mt = 0; mt < 4; mt++) {
                const int row = wm * 64 + mt * 16 + lr + (lg & 1) * 8;
                const int ch = kk * 2 + (lg >> 1);
                ldsm_x4(a4[mt][0], a4[mt][1], a4[mt][2], a4[mt][3],
                        swz8(sX, row, ch));
            }
            uint32_t b4[8][2];
#pragma unroll
            for (int np = 0; np < 4; np++) {
                const int row = wn * 64 + np * 16 + lr + (lg >> 1) * 8;
                const int ch = kk * 2 + (lg & 1);
                ldsm_x4(b4[np * 2][0], b4[np * 2][1], b4[np * 2 + 1][0],
                        b4[np * 2 + 1][1], swz8(sB, row, ch));
            }
#pragma unroll
            for (int mt = 0; mt < 4; mt++)
#pragma unroll
                for (int nt = 0; nt < 8; nt++)
                    mma16816(acc[mt][nt], a4[mt], b4[nt]);
        }
    }
    __syncthreads();
}

// fused QKV: z=0 -> Q (scaled); z=1 -> K; z=2 -> V
__global__ __launch_bounds__(128, 2) void gemm_qkv(
    const __half* __restrict__ Xf, const __half* __restrict__ Wq,
    const __half* __restrict__ Wk, const __half* __restrict__ Wv,
    __half* __restrict__ Qf, __half* __restrict__ Kf, __half* __restrict__ Vf) {
    extern __shared__ char sm[];
    const uint32_t sb = smem_u32(sm);
    const int tid = threadIdx.x;
    const int lane = tid & 31;
    const int wid = tid >> 5;
    const int z = blockIdx.z;
    const int bm = blockIdx.y * BM;
    const int bn = blockIdx.x * BN;

    const __half* Bf = (z == 0) ? Wq : (z == 1) ? Wk : Wv;

    float acc[4][8][4];
    gemm_core1(sb, Xf, Bf, bm, bn, tid, acc);

    const int wm = wid & 1;
    const int wn = wid >> 1;
    __half* Dst = (z == 0) ? Qf : (z == 1) ? Kf : Vf;
    const float s = (z == 0) ? (QK_SCALE * INV_WSCALE) : INV_WSCALE;
#pragma unroll
    for (int mt = 0; mt < 4; mt++) {
        const int row = bm + wm * 64 + mt * 16 + (lane >> 2);
#pragma unroll
        for (int nt = 0; nt < 8; nt++) {
            const int col = bn + wn * 64 + nt * 8 + (lane & 3) * 2;
            *reinterpret_cast<uint32_t*>(&Dst[(size_t)row * D_EMB + col]) =
                pack_f16(acc[mt][nt][0] * s, acc[mt][nt][1] * s);
            *reinterpret_cast<uint32_t*>(&Dst[(size_t)(row + 8) * D_EMB + col]) =
                pack_f16(acc[mt][nt][2] * s, acc[mt][nt][3] * s);
        }
    }
}

// out-projection: fp32 output
__global__ __launch_bounds__(128, 2) void gemm_out(
    const __half* __restrict__ Af, const __half* __restrict__ Bf,
    float* __restrict__ C) {
    extern __shared__ char sm[];
    const uint32_t sb = smem_u32(sm);
    const int tid = threadIdx.x;
    const int lane = tid & 31;
    const int wid = tid >> 5;
    const int bm = blockIdx.y * BM;
    const int bn = blockIdx.x * BN;

    float acc[4][8][4];
    gemm_core1(sb, Af, Bf, bm, bn, tid, acc);

    const int wm = wid & 1;
    const int wn = wid >> 1;
#pragma unroll
    for (int mt = 0; mt < 4; mt++) {
        const int row = bm + wm * 64 + mt * 16 + (lane >> 2);
#pragma unroll
        for (int nt = 0; nt < 8; nt++) {
            const int col = bn + wn * 64 + nt * 8 + (lane & 3) * 2;
            *reinterpret_cast<float2*>(&C[(size_t)row * D_EMB + col]) =
                make_float2(acc[mt][nt][0] * INV_WSCALE, acc[mt][nt][1] * INV_WSCALE);
            *reinterpret_cast<float2*>(&C[(size_t)(row + 8) * D_EMB + col]) =
                make_float2(acc[mt][nt][2] * INV_WSCALE, acc[mt][nt][3] * INV_WSCALE);
        }
    }
}

// ---------------- fp16 HMMA flash attention (round-9 config) ----------------
#define ATTN_SMEM 65536

__global__ __launch_bounds__(128, 2) void attn_mma(
    const __half* __restrict__ Qf, const __half* __restrict__ Kf,
    const __half* __restrict__ Vf, __half* __restrict__ Rf) {
    extern __shared__ char sm[];
    const uint32_t sb = smem_u32(sm);
    const uint32_t sQ = sb;
    const uint32_t sK = sb + 32768;
    const uint32_t sV = sb + 49152;

    const int n = blockIdx.y;
    const int m0 = blockIdx.x * 128;
    const int tid = threadIdx.x;
    const int lane = tid & 31;
    const int w = tid >> 5;
    const int lr = lane & 7;
    const int lg = lane >> 3;

    for (int u = tid; u < 2048; u += 128) {
        const int row = u >> 4, ch = u & 15;
        const uint32_t d = (uint32_t)((row * 16 + (ch ^ (row & 7))) * 16);
        CP_ASYNC16(sQ + d, Qf + (size_t)(m0 + row) * D_EMB + n * HD + ch * 8);
    }
    CP_COMMIT();
    for (int u = tid; u < 1024; u += 128) {
        const int row = u >> 4, ch = u & 15;
        const uint32_t d = (uint32_t)((row * 16 + (ch ^ (row & 7))) * 16);
        CP_ASYNC16(sK + d, Kf + (size_t)row * D_EMB + n * HD + ch * 8);
    }
    CP_COMMIT();
    for (int u = tid; u < 1024; u += 128) {
        const int row = u >> 4, ch = u & 15;
        const uint32_t d = (uint32_t)((row * 16 + (ch ^ (row & 7))) * 16);
        CP_ASYNC16(sV + d, Vf + (size_t)row * D_EMB + n * HD + ch * 8);
    }
    CP_COMMIT();

    float acc[2][16][4];
#pragma unroll
    for (int mt = 0; mt < 2; mt++)
#pragma unroll
        for (int ht = 0; ht < 16; ht++)
#pragma unroll
            for (int e = 0; e < 4; e++) acc[mt][ht][e] = 0.0f;
    float M0[2] = {-1e30f, -1e30f}, M1[2] = {-1e30f, -1e30f};
    float L0[2] = {0.0f, 0.0f}, L1[2] = {0.0f, 0.0f};

    const int NT = T_SEQ / 64;
    for (int it = 0; it < NT; it++) {
        CP_WAIT(1);
        __syncthreads();

        float c[2][8][4];
#pragma unroll
        for (int mt = 0; mt < 2; mt++)
#pragma unroll
            for (int t = 0; t < 8; t++)
#pragma unroll
                for (int e = 0; e < 4; e++) c[mt][t][e] = 0.0f;

#pragma unroll
        for (int kk = 0; kk < 8; kk++) {
            uint32_t q4[2][4];
#pragma unroll
            for (int mt = 0; mt < 2; mt++) {
                const int row = w * 32 + mt * 16 + lr + (lg & 1) * 8;
                const int ch = kk * 2 + (lg >> 1);
                const uint32_t a = (uint32_t)((row * 16 + (ch ^ (row & 7))) * 16);
                ldsm_x4(q4[mt][0], q4[mt][1], q4[mt][2], q4[mt][3], sQ + a);
            }
#pragma unroll
            for (int np = 0; np < 4; np++) {
                uint32_t k4[4];
                const int row = np * 16 + lr + (lg >> 1) * 8;
                const int ch = kk * 2 + (lg & 1);
                const uint32_t a = (uint32_t)((row * 16 + (ch ^ (row & 7))) * 16);
                ldsm_x4(k4[0], k4[1], k4[2], k4[3], sK + a);
#pragma unroll
                for (int mt = 0; mt < 2; mt++) {
                    mma16816(c[mt][np * 2],     q4[mt], &k4[0]);
                    mma16816(c[mt][np * 2 + 1], q4[mt], &k4[2]);
                }
            }
        }
        __syncthreads();

        if (it + 1 < NT) {
            for (int u = tid; u < 1024; u += 128) {
                const int row = u >> 4, ch = u & 15;
                const uint32_t d = (uint32_t)((row * 16 + (ch ^ (row & 7))) * 16);
                CP_ASYNC16(sK + d, Kf + (size_t)((it + 1) * 64 + row) * D_EMB +
                                       n * HD + ch * 8);
            }
            CP_COMMIT();
        }

#pragma unroll
        for (int mt = 0; mt < 2; mt++) {
            float mx0 = -1e30f, mx1 = -1e30f;
#pragma unroll
            for (int t = 0; t < 8; t++) {
                mx0 = fmaxf(mx0, fmaxf(c[mt][t][0], c[mt][t][1]));
                mx1 = fmaxf(mx1, fmaxf(c[mt][t][2], c[mt][t][3]));
            }
            mx0 = fmaxf(mx0, __shfl_xor_sync(0xffffffffu, mx0, 1));
            mx0 = fmaxf(mx0, __shfl_xor_sync(0xffffffffu, mx0, 2));
            mx1 = fmaxf(mx1, __shfl_xor_sync(0xffffffffu, mx1, 1));
            mx1 = fmaxf(mx1, __shfl_xor_sync(0xffffffffu, mx1, 2));

            const float Mn0 = fmaxf(M0[mt], mx0), Mn1 = fmaxf(M1[mt], mx1);
            const float a0 = __expf(M0[mt] - Mn0), a1 = __expf(M1[mt] - Mn1);
            float sum0 = 0.0f, sum1 = 0.0f;
#pragma unroll
            for (int t = 0; t < 8; t++) {
                c[mt][t][0] = __expf(c[mt][t][0] - Mn0);
                c[mt][t][1] = __expf(c[mt][t][1] - Mn0);
                c[mt][t][2] = __expf(c[mt][t][2] - Mn1);
                c[mt][t][3] = __expf(c[mt][t][3] - Mn1);
                sum0 += c[mt][t][0] + c[mt][t][1];
                sum1 += c[mt][t][2] + c[mt][t][3];
            }
            sum0 += __shfl_xor_sync(0xffffffffu, sum0, 1);
            sum0 += __shfl_xor_sync(0xffffffffu, sum0, 2);
            sum1 += __shfl_xor_sync(0xffffffffu, sum1, 1);
            sum1 += __shfl_xor_sync(0xffffffffu, sum1, 2);
            L0[mt] = L0[mt] * a0 + sum0;
            L1[mt] = L1[mt] * a1 + sum1;
            M0[mt] = Mn0;
            M1[mt] = Mn1;
#pragma unroll
            for (int ht = 0; ht < 16; ht++) {
                acc[mt][ht][0] *= a0;
                acc[mt][ht][1] *= a0;
                acc[mt][ht][2] *= a1;
                acc[mt][ht][3] *= a1;
            }
        }

        if (it + 1 < NT) {
            CP_WAIT(1);
        } else {
            CP_WAIT(0);
        }
        __syncthreads();

#pragma unroll
        for (int kk = 0; kk < 4; kk++) {
            uint32_t ap[2][4];
#pragma unroll
            for (int mt = 0; mt < 2; mt++) {
                const int t0 = kk * 2, t1 = kk * 2 + 1;
                ap[mt][0] = pack_f16(c[mt][t0][0], c[mt][t0][1]);
                ap[mt][1] = pack_f16(c[mt][t0][2], c[mt][t0][3]);
                ap[mt][2] = pack_f16(c[mt][t1][0], c[mt][t1][1]);
                ap[mt][3] = pack_f16(c[mt][t1][2], c[mt][t1][3]);
            }
#pragma unroll
            for (int hq = 0; hq < 8; hq++) {
                uint32_t v4[4];
                const int row = kk * 16 + (lg & 1) * 8 + lr;
                const int ch = hq * 2 + (lg >> 1);
                const uint32_t a = (uint32_t)((row * 16 + (ch ^ (row & 7))) * 16);
                ldsm_x4_t(v4[0], v4[1], v4[2], v4[3], sV + a);
#pragma unroll
                for (int mt = 0; mt < 2; mt++) {
                    mma16816(acc[mt][hq * 2],     ap[mt], &v4[0]);
                    mma16816(acc[mt][hq * 2 + 1], ap[mt], &v4[2]);
                }
            }
        }
        __syncthreads();

        if (it + 1 < NT) {
            for (int u = tid; u < 1024; u += 128) {
                const int row = u >> 4, ch = u & 15;
                const uint32_t d = (uint32_t)((row * 16 + (ch ^ (row & 7))) * 16);
                CP_ASYNC16(sV + d, Vf + (size_t)((it + 1) * 64 + row) * D_EMB +
                                       n * HD + ch * 8);
            }
            CP_COMMIT();
        }
    }

#pragma unroll
    for (int mt = 0; mt < 2; mt++) {
        const float i0 = 1.0f / L0[mt], i1 = 1.0f / L1[mt];
        const int rowg = m0 + w * 32 + mt * 16 + (lane >> 2);
#pragma unroll
        for (int ht = 0; ht < 16; ht++) {
            const int col = n * HD + ht * 8 + (lane & 3) * 2;
            *reinterpret_cast<uint32_t*>(&Rf[(size_t)rowg * D_EMB + col]) =
                pack_f16(acc[mt][ht][0] * i0, acc[mt][ht][1] * i0);
            *reinterpret_cast<uint32_t*>(&Rf[(size_t)(rowg + 8) * D_EMB + col]) =
                pack_f16(acc[mt][ht][2] * i1, acc[mt][ht][3] * i1);
        }
    }
}

// ---------------------------------------------------------------------------
extern "C" void kernel_launch(void* const* d_in, const int* in_sizes, int n_in,
                              void* d_out, int out_size) {
    const float* X  = (const float*)d_in[0];
    const float* Wq = (const float*)d_in[1];
    const float* Wk = (const float*)d_in[2];
    const float* Wv = (const float*)d_in[3];
    const float* Wo = (const float*)d_in[4];
    float* out = (float*)d_out;

    __half *xf, *rf, *qf, *kf, *vf, *wq, *wk, *wv, *wo;
    cudaGetSymbolAddress((void**)&xf, g_Xf);
    cudaGetSymbolAddress((void**)&rf, g_Rf);
    cudaGetSymbolAddress((void**)&qf, g_Qf);
    cudaGetSymbolAddress((void**)&kf, g_Kf);
    cudaGetSymbolAddress((void**)&vf, g_Vf);
    cudaGetSymbolAddress((void**)&wq, g_Wq);
    cudaGetSymbolAddress((void**)&wk, g_Wk);
    cudaGetSymbolAddress((void**)&wv, g_Wv);
    cudaGetSymbolAddress((void**)&wo, g_Wo);

    const int NELE4 = T_SEQ * D_EMB / 4 / 256;

    convX<<<NELE4, 256>>>(X, xf);
    convW16all<<<dim3(64, 32, 4), dim3(32, 8)>>>(Wq, Wk, Wv, Wo, wq, wk, wv, wo);

    cudaFuncSetAttribute(gemm_qkv, cudaFuncAttributeMaxDynamicSharedMemorySize,
                         GEMM_SMEM);
    cudaFuncSetAttribute(gemm_out, cudaFuncAttributeMaxDynamicSharedMemorySize,
                         GEMM_SMEM);
    gemm_qkv<<<dim3(D_EMB / BN, T_SEQ / BM, 3), 128, GEMM_SMEM>>>(xf, wq, wk, wv,
                                                                  qf, kf, vf);

    cudaFuncSetAttribute(attn_mma, cudaFuncAttributeMaxDynamicSharedMemorySize,
                         ATTN_SMEM);
    attn_mma<<<dim3(T_SEQ / 128, NHEADS), 128, ATTN_SMEM>>>(qf, kf, vf, rf);

    gemm_out<<<dim3(D_EMB / BN, T_SEQ / BM), 128, GEMM_SMEM>>>(rf, wo, out);
}

// round 14
// speedup vs baseline: 1.0980x; 1.0346x over previous
#include <cuda_runtime.h>
#include <cuda_fp16.h>
#include <stdint.h>
#include <math.h>

#define T_SEQ 2048
#define D_EMB 2048
#define HD    128
#define NHEADS 16
#define QK_SCALE 0.08838834764831843f
#define WSCALE 256.0f
#define INV_WSCALE (1.0f / 256.0f)

// ---------------- scratch (no allocs allowed) ----------------
__device__ __half g_Xf[T_SEQ * D_EMB];
__device__ __half g_Rf[T_SEQ * D_EMB];
// weights in NATURAL layout (x256, fp16): Wq/Wk/Wv = [n][k][j], Wo = [k][j]
__device__ __half g_Wq[D_EMB * D_EMB];
__device__ __half g_Wk[D_EMB * D_EMB];
__device__ __half g_Wv[D_EMB * D_EMB];
__device__ __half g_Wo[D_EMB * D_EMB];
__device__ __half g_Qf[T_SEQ * D_EMB];
__device__ __half g_Kf[T_SEQ * D_EMB];
__device__ __half g_Vf[T_SEQ * D_EMB];

// ---------------- PTX helpers (base sm_103-legal only) ----------------
__device__ __forceinline__ uint32_t smem_u32(const void* p) {
    uint32_t a;
    asm("{ .reg .u64 t; cvta.to.shared.u64 t, %1; cvt.u32.u64 %0, t; }"
        : "=r"(a) : "l"(p));
    return a;
}
#define CP_ASYNC16(dst, src) \
    asm volatile("cp.async.cg.shared.global [%0], [%1], 16;" :: "r"(dst), "l"(src))
#define CP_COMMIT() asm volatile("cp.async.commit_group;" ::: "memory")
#define CP_WAIT(n) asm volatile("cp.async.wait_group %0;" :: "n"(n) : "memory")

__device__ __forceinline__ void ldsm_x4(uint32_t& r0, uint32_t& r1, uint32_t& r2,
                                        uint32_t& r3, uint32_t addr) {
    asm volatile("ldmatrix.sync.aligned.m8n8.x4.shared.b16 {%0,%1,%2,%3}, [%4];"
                 : "=r"(r0), "=r"(r1), "=r"(r2), "=r"(r3) : "r"(addr));
}
__device__ __forceinline__ void ldsm_x4_t(uint32_t& r0, uint32_t& r1, uint32_t& r2,
                                          uint32_t& r3, uint32_t addr) {
    asm volatile(
        "ldmatrix.sync.aligned.m8n8.x4.trans.shared.b16 {%0,%1,%2,%3}, [%4];"
        : "=r"(r0), "=r"(r1), "=r"(r2), "=r"(r3) : "r"(addr));
}
__device__ __forceinline__ void mma16816(float* c, const uint32_t* a,
                                         const uint32_t* b) {
    asm volatile(
        "mma.sync.aligned.m16n8k16.row.col.f32.f16.f16.f32 "
        "{%0,%1,%2,%3}, {%4,%5,%6,%7}, {%8,%9}, {%0,%1,%2,%3};"
        : "+f"(c[0]), "+f"(c[1]), "+f"(c[2]), "+f"(c[3])
        : "r"(a[0]), "r"(a[1]), "r"(a[2]), "r"(a[3]), "r"(b[0]), "r"(b[1]));
}
__device__ __forceinline__ uint32_t pack_f16(float x, float y) {
    __half2 h = __floats2half2_rn(x, y);
    return *reinterpret_cast<uint32_t*>(&h);
}

// ---------------- conversion kernels (pure streaming) ----------------
__global__ __launch_bounds__(256) void convX(const float* __restrict__ A,
                                             __half* __restrict__ F) {
    const int i = blockIdx.x * 256 + threadIdx.x;
    float4 v = reinterpret_cast<const float4*>(A)[i];
    __half f[4] = {__float2half_rn(v.x), __float2half_rn(v.y),
                   __float2half_rn(v.z), __float2half_rn(v.w)};
    reinterpret_cast<uint2*>(F)[i] = *reinterpret_cast<uint2*>(f);
}

// elementwise weight conversion (natural layout preserved), x256
__global__ __launch_bounds__(256) void convWflat(
    const float* __restrict__ Wq, const float* __restrict__ Wk,
    const float* __restrict__ Wv, const float* __restrict__ Wo,
    __half* __restrict__ Hq, __half* __restrict__ Hk,
    __half* __restrict__ Hv, __half* __restrict__ Ho) {
    const int z = blockIdx.y;
    const float* W = (z == 0) ? Wq : (z == 1) ? Wk : (z == 2) ? Wv : Wo;
    __half* H = (z == 0) ? Hq : (z == 1) ? Hk : (z == 2) ? Hv : Ho;
    const int i = blockIdx.x * 256 + threadIdx.x;
    float4 v = reinterpret_cast<const float4*>(W)[i];
    __half f[4] = {__float2half_rn(v.x * WSCALE), __float2half_rn(v.y * WSCALE),
                   __float2half_rn(v.z * WSCALE), __float2half_rn(v.w * WSCALE)};
    reinterpret_cast<uint2*>(H)[i] = *reinterpret_cast<uint2*>(f);
}

// ---------------- 1-pass fp16 HMMA GEMM (trans-B from natural layout) --------
// CTA 128x128, BK=64, 128 threads (2x2 warps of 64x64), 2 CTAs/SM, 3-stage.
// A tile: [128 m][64 k] halves, 128B rows, 8 chunks, swz8.
// B tile: [64 k][128 n] halves, 256B rows, 16 chunks, attention-V swizzle.
#define BM 128
#define BN 128
#define BK 64
#define STAGE_B 32768  // A 16K + B 16K
#define GEMM_SMEM (3 * STAGE_B)

__device__ __forceinline__ uint32_t swz8(uint32_t base, int row, int chunk) {
    return base + (((row << 3) + (chunk ^ (row & 7))) << 4);
}
__device__ __forceinline__ uint32_t swzB(uint32_t base, int row, int chunk) {
    return base + (((row << 4) + (chunk ^ (row & 7))) << 4);
}

__device__ __forceinline__ void stage_all(uint32_t sbase, const __half* Af,
                                          const __half* Bp, int bstride, int bm,
                                          int k0, int tid) {
    // A: 128 rows x 8 chunks
#pragma unroll
    for (int u = tid; u < 1024; u += 128) {
        const int row = u >> 3, ch = u & 7;
        CP_ASYNC16(swz8(sbase, row, ch),
                   Af + (size_t)(bm + row) * D_EMB + k0 + ch * 8);
    }
    // B: 64 k-rows x 16 chunks (natural [k][n] layout)
#pragma unroll
    for (int u = tid; u < 1024; u += 128) {
        const int row = u >> 4, ch = u & 15;
        CP_ASYNC16(swzB(sbase + 16384, row, ch),
                   Bp + (size_t)(k0 + row) * bstride + ch * 8);
    }
    CP_COMMIT();
}

__device__ __forceinline__ void gemm_core1(
    uint32_t sb, const __half* Af, const __half* Bp, int bstride, int bm,
    int tid, float acc[4][8][4]) {
    const int lane = tid & 31;
    const int wid = tid >> 5;
    const int wm = wid & 1;
    const int wn = wid >> 1;
    const int lr = lane & 7;
    const int lg = lane >> 3;

#pragma unroll
    for (int mt = 0; mt < 4; mt++)
#pragma unroll
        for (int nt = 0; nt < 8; nt++)
#pragma unroll
            for (int e = 0; e < 4; e++) acc[mt][nt][e] = 0.0f;

    stage_all(sb + 0 * STAGE_B, Af, Bp, bstride, bm, 0, tid);
    stage_all(sb + 1 * STAGE_B, Af, Bp, bstride, bm, BK, tid);

    const int NITER = D_EMB / BK;  // 32
    for (int c = 0; c < NITER; c++) {
        if (c == NITER - 1) {
            CP_WAIT(0);
        } else {
            CP_WAIT(1);
        }
        __syncthreads();
        if (c + 2 < NITER)
            stage_all(sb + ((c + 2) % 3) * STAGE_B, Af, Bp, bstride, bm,
                      (c + 2) * BK, tid);

        const uint32_t sX = sb + (c % 3) * STAGE_B;
        const uint32_t sB = sX + 16384;

#pragma unroll
        for (int kk = 0; kk < 4; kk++) {
            uint32_t a4[4][4];
#pragma unroll
            for (int mt = 0; mt < 4; mt++) {
                const int row = wm * 64 + mt * 16 + lr + (lg & 1) * 8;
                const int ch = kk * 2 + (lg >> 1);
                ldsm_x4(a4[mt][0], a4[mt][1], a4[mt][2], a4[mt][3],
                        swz8(sX, row, ch));
            }
            uint32_t b4[8][2];
#pragma unroll
            for (int nt = 0; nt < 8; nt += 2) {
                uint32_t v0, v1, v2, v3;
                const int row = kk * 16 + (lg & 1) * 8 + lr;
                const int ch = wn * 8 + nt + (lg >> 1);
                ldsm_x4_t(v0, v1, v2, v3, swzB(sB, row, ch));
                b4[nt][0] = v0;
                b4[nt][1] = v1;
                b4[nt + 1][0] = v2;
                b4[nt + 1][1] = v3;
            }
#pragma unroll
            for (int mt = 0; mt < 4; mt++)
#pragma unroll
                for (int nt = 0; nt < 8; nt++)
                    mma16816(acc[mt][nt], a4[mt], b4[nt]);
        }
    }
    __syncthreads();
}

// fused QKV: z=0 -> Q (scaled); z=1 -> K; z=2 -> V
__global__ __launch_bounds__(128, 2) void gemm_qkv(
    const __half* __restrict__ Xf, const __half* __restrict__ Wq,
    const __half* __restrict__ Wk, const __half* __restrict__ Wv,
    __half* __restrict__ Qf, __half* __restrict__ Kf, __half* __restrict__ Vf) {
    extern __shared__ char sm[];
    const uint32_t sb = smem_u32(sm);
    const int tid = threadIdx.x;
    const int lane = tid & 31;
    const int wid = tid >> 5;
    const int z = blockIdx.z;
    const int bm = blockIdx.y * BM;
    const int bn = blockIdx.x * BN;

    const __half* W = (z == 0) ? Wq : (z == 1) ? Wk : Wv;
    // BN == HD: tile sits inside head (bn >> 7); per-head block is [D_EMB][HD]
    const __half* Bp = W + (size_t)(bn >> 7) * D_EMB * HD;

    float acc[4][8][4];
    gemm_core1(sb, Xf, Bp, HD, bm, tid, acc);

    const int wm = wid & 1;
    const int wn = wid >> 1;
    __half* Dst = (z == 0) ? Qf : (z == 1) ? Kf : Vf;
    const float s = (z == 0) ? (QK_SCALE * INV_WSCALE) : INV_WSCALE;
#pragma unroll
    for (int mt = 0; mt < 4; mt++) {
        const int row = bm + wm * 64 + mt * 16 + (lane >> 2);
#pragma unroll
        for (int nt = 0; nt < 8; nt++) {
            const int col = bn + wn * 64 + nt * 8 + (lane & 3) * 2;
            *reinterpret_cast<uint32_t*>(&Dst[(size_t)row * D_EMB + col]) =
                pack_f16(acc[mt][nt][0] * s, acc[mt][nt][1] * s);
            *reinterpret_cast<uint32_t*>(&Dst[(size_t)(row + 8) * D_EMB + col]) =
                pack_f16(acc[mt][nt][2] * s, acc[mt][nt][3] * s);
        }
    }
}

// out-projection: fp32 output
__global__ __launch_bounds__(128, 2) void gemm_out(
    const __half* __restrict__ Af, const __half* __restrict__ Wo,
    float* __restrict__ C) {
    extern __shared__ char sm[];
    const uint32_t sb = smem_u32(sm);
    const int tid = threadIdx.x;
    const int lane = tid & 31;
    const int wid = tid >> 5;
    const int bm = blockIdx.y * BM;
    const int bn = blockIdx.x * BN;

    const __half* Bp = Wo + bn;  // [k][j] natural, row stride D_EMB

    float acc[4][8][4];
    gemm_core1(sb, Af, Bp, D_EMB, bm, tid, acc);

    const int wm = wid & 1;
    const int wn = wid >> 1;
#pragma unroll
    for (int mt = 0; mt < 4; mt++) {
        const int row = bm + wm * 64 + mt * 16 + (lane >> 2);
#pragma unroll
        for (int nt = 0; nt < 8; nt++) {
            const int col = bn + wn * 64 + nt * 8 + (lane & 3) * 2;
            *reinterpret_cast<float2*>(&C[(size_t)row * D_EMB + col]) =
                make_float2(acc[mt][nt][0] * INV_WSCALE, acc[mt][nt][1] * INV_WSCALE);
            *reinterpret_cast<float2*>(&C[(size_t)(row + 8) * D_EMB + col]) =
                make_float2(acc[mt][nt][2] * INV_WSCALE, acc[mt][nt][3] * INV_WSCALE);
        }
    }
}

// ---------------- fp16 HMMA flash attention (round-9 config) ----------------
#define ATTN_SMEM 65536

__global__ __launch_bounds__(128, 2) void attn_mma(
    const __half* __restrict__ Qf, const __half* __restrict__ Kf,
    const __half* __restrict__ Vf, __half* __restrict__ Rf) {
    extern __shared__ char sm[];
    const uint32_t sb = smem_u32(sm);
    const uint32_t sQ = sb;
    const uint32_t sK = sb + 32768;
    const uint32_t sV = sb + 49152;

    const int n = blockIdx.y;
    const int m0 = blockIdx.x * 128;
    const int tid = threadIdx.x;
    const int lane = tid & 31;
    const int w = tid >> 5;
    const int lr = lane & 7;
    const int lg = lane >> 3;

    for (int u = tid; u < 2048; u += 128) {
        const int row = u >> 4, ch = u & 15;
        const uint32_t d = (uint32_t)((row * 16 + (ch ^ (row & 7))) * 16);
        CP_ASYNC16(sQ + d, Qf + (size_t)(m0 + row) * D_EMB + n * HD + ch * 8);
    }
    CP_COMMIT();
    for (int u = tid; u < 1024; u += 128) {
        const int row = u >> 4, ch = u & 15;
        const uint32_t d = (uint32_t)((row * 16 + (ch ^ (row & 7))) * 16);
        CP_ASYNC16(sK + d, Kf + (size_t)row * D_EMB + n * HD + ch * 8);
    }
    CP_COMMIT();
    for (int u = tid; u < 1024; u += 128) {
        const int row = u >> 4, ch = u & 15;
        const uint32_t d = (uint32_t)((row * 16 + (ch ^ (row & 7))) * 16);
        CP_ASYNC16(sV + d, Vf + (size_t)row * D_EMB + n * HD + ch * 8);
    }
    CP_COMMIT();

    float acc[2][16][4];
#pragma unroll
    for (int mt = 0; mt < 2; mt++)
#pragma unroll
        for (int ht = 0; ht < 16; ht++)
#pragma unroll
            for (int e = 0; e < 4; e++) acc[mt][ht][e] = 0.0f;
    float M0[2] = {-1e30f, -1e30f}, M1[2] = {-1e30f, -1e30f};
    float L0[2] = {0.0f, 0.0f}, L1[2] = {0.0f, 0.0f};

    const int NT = T_SEQ / 64;
    for (int it = 0; it < NT; it++) {
        CP_WAIT(1);
        __syncthreads();

        float c[2][8][4];
#pragma unroll
        for (int mt = 0; mt < 2; mt++)
#pragma unroll
            for (int t = 0; t < 8; t++)
#pragma unroll
                for (int e = 0; e < 4; e++) c[mt][t][e] = 0.0f;

#pragma unroll
        for (int kk = 0; kk < 8; kk++) {
            uint32_t q4[2][4];
#pragma unroll
            for (int mt = 0; mt < 2; mt++) {
                const int row = w * 32 + mt * 16 + lr + (lg & 1) * 8;
                const int ch = kk * 2 + (lg >> 1);
                const uint32_t a = (uint32_t)((row * 16 + (ch ^ (row & 7))) * 16);
                ldsm_x4(q4[mt][0], q4[mt][1], q4[mt][2], q4[mt][3], sQ + a);
            }
#pragma unroll
            for (int np = 0; np < 4; np++) {
                uint32_t k4[4];
                const int row = np * 16 + lr + (lg >> 1) * 8;
                const int ch = kk * 2 + (lg & 1);
                const uint32_t a = (uint32_t)((row * 16 + (ch ^ (row & 7))) * 16);
                ldsm_x4(k4[0], k4[1], k4[2], k4[3], sK + a);
#pragma unroll
                for (int mt = 0; mt < 2; mt++) {
                    mma16816(c[mt][np * 2],     q4[mt], &k4[0]);
                    mma16816(c[mt][np * 2 + 1], q4[mt], &k4[2]);
                }
            }
        }
        __syncthreads();

        if (it + 1 < NT) {
            for (int u = tid; u < 1024; u += 128) {
                const int row = u >> 4, ch = u & 15;
                const uint32_t d = (uint32_t)((row * 16 + (ch ^ (row & 7))) * 16);
                CP_ASYNC16(sK + d, Kf + (size_t)((it + 1) * 64 + row) * D_EMB +
                                       n * HD + ch * 8);
            }
            CP_COMMIT();
        }

#pragma unroll
        for (int mt = 0; mt < 2; mt++) {
            float mx0 = -1e30f, mx1 = -1e30f;
#pragma unroll
            for (int t = 0; t < 8; t++) {
                mx0 = fmaxf(mx0, fmaxf(c[mt][t][0], c[mt][t][1]));
                mx1 = fmaxf(mx1, fmaxf(c[mt][t][2], c[mt][t][3]));
            }
            mx0 = fmaxf(mx0, __shfl_xor_sync(0xffffffffu, mx0, 1));
            mx0 = fmaxf(mx0, __shfl_xor_sync(0xffffffffu, mx0, 2));
            mx1 = fmaxf(mx1, __shfl_xor_sync(0xffffffffu, mx1, 1));
            mx1 = fmaxf(mx1, __shfl_xor_sync(0xffffffffu, mx1, 2));

            const float Mn0 = fmaxf(M0[mt], mx0), Mn1 = fmaxf(M1[mt], mx1);
            const float a0 = __expf(M0[mt] - Mn0), a1 = __expf(M1[mt] - Mn1);
            float sum0 = 0.0f, sum1 = 0.0f;
#pragma unroll
            for (int t = 0; t < 8; t++) {
                c[mt][t][0] = __expf(c[mt][t][0] - Mn0);
                c[mt][t][1] = __expf(c[mt][t][1] - Mn0);
                c[mt][t][2] = __expf(c[mt][t][2] - Mn1);
                c[mt][t][3] = __expf(c[mt][t][3] - Mn1);
                sum0 += c[mt][t][0] + c[mt][t][1];
                sum1 += c[mt][t][2] + c[mt][t][3];
            }
            sum0 += __shfl_xor_sync(0xffffffffu, sum0, 1);
            sum0 += __shfl_xor_sync(0xffffffffu, sum0, 2);
            sum1 += __shfl_xor_sync(0xffffffffu, sum1, 1);
            sum1 += __shfl_xor_sync(0xffffffffu, sum1, 2);
            L0[mt] = L0[mt] * a0 + sum0;
            L1[mt] = L1[mt] * a1 + sum1;
            M0[mt] = Mn0;
            M1[mt] = Mn1;
#pragma unroll
            for (int ht = 0; ht < 16; ht++) {
                acc[mt][ht][0] *= a0;
                acc[mt][ht][1] *= a0;
                acc[mt][ht][2] *= a1;
                acc[mt][ht][3] *= a1;
            }
        }

        if (it + 1 < NT) {
            CP_WAIT(1);
        } else {
            CP_WAIT(0);
        }
        __syncthreads();

#pragma unroll
        for (int kk = 0; kk < 4; kk++) {
            uint32_t ap[2][4];
#pragma unroll
            for (int mt = 0; mt < 2; mt++) {
                const int t0 = kk * 2, t1 = kk * 2 + 1;
                ap[mt][0] = pack_f16(c[mt][t0][0], c[mt][t0][1]);
                ap[mt][1] = pack_f16(c[mt][t0][2], c[mt][t0][3]);
                ap[mt][2] = pack_f16(c[mt][t1][0], c[mt][t1][1]);
                ap[mt][3] = pack_f16(c[mt][t1][2], c[mt][t1][3]);
            }
#pragma unroll
            for (int hq = 0; hq < 8; hq++) {
                uint32_t v4[4];
                const int row = kk * 16 + (lg & 1) * 8 + lr;
                const int ch = hq * 2 + (lg >> 1);
                const uint32_t a = (uint32_t)((row * 16 + (ch ^ (row & 7))) * 16);
                ldsm_x4_t(v4[0], v4[1], v4[2], v4[3], sV + a);
#pragma unroll
                for (int mt = 0; mt < 2; mt++) {
                    mma16816(acc[mt][hq * 2],     ap[mt], &v4[0]);
                    mma16816(acc[mt][hq * 2 + 1], ap[mt], &v4[2]);
                }
            }
        }
        __syncthreads();

        if (it + 1 < NT) {
            for (int u = tid; u < 1024; u += 128) {
                const int row = u >> 4, ch = u & 15;
                const uint32_t d = (uint32_t)((row * 16 + (ch ^ (row & 7))) * 16);
                CP_ASYNC16(sV + d, Vf + (size_t)((it + 1) * 64 + row) * D_EMB +
                                       n * HD + ch * 8);
            }
            CP_COMMIT();
        }
    }

#pragma unroll
    for (int mt = 0; mt < 2; mt++) {
        const float i0 = 1.0f / L0[mt], i1 = 1.0f / L1[mt];
        const int rowg = m0 + w * 32 + mt * 16 + (lane >> 2);
#pragma unroll
        for (int ht = 0; ht < 16; ht++) {
            const int col = n * HD + ht * 8 + (lane & 3) * 2;
            *reinterpret_cast<uint32_t*>(&Rf[(size_t)rowg * D_EMB + col]) =
                pack_f16(acc[mt][ht][0] * i0, acc[mt][ht][1] * i0);
            *reinterpret_cast<uint32_t*>(&Rf[(size_t)(rowg + 8) * D_EMB + col]) =
                pack_f16(acc[mt][ht][2] * i1, acc[mt][ht][3] * i1);
        }
    }
}

// ---------------------------------------------------------------------------
extern "C" void kernel_launch(void* const* d_in, const int* in_sizes, int n_in,
                              void* d_out, int out_size) {
    const float* X  = (const float*)d_in[0];
    const float* Wq = (const float*)d_in[1];
    const float* Wk = (const float*)d_in[2];
    const float* Wv = (const float*)d_in[3];
    const float* Wo = (const float*)d_in[4];
    float* out = (float*)d_out;

    __half *xf, *rf, *qf, *kf, *vf, *wq, *wk, *wv, *wo;
    cudaGetSymbolAddress((void**)&xf, g_Xf);
    cudaGetSymbolAddress((void**)&rf, g_Rf);
    cudaGetSymbolAddress((void**)&qf, g_Qf);
    cudaGetSymbolAddress((void**)&kf, g_Kf);
    cudaGetSymbolAddress((void**)&vf, g_Vf);
    cudaGetSymbolAddress((void**)&wq, g_Wq);
    cudaGetSymbolAddress((void**)&wk, g_Wk);
    cudaGetSymbolAddress((void**)&wv, g_Wv);
    cudaGetSymbolAddress((void**)&wo, g_Wo);

    const int NELE4 = T_SEQ * D_EMB / 4 / 256;

    convX<<<NELE4, 256>>>(X, xf);
    convWflat<<<dim3(NELE4, 4), 256>>>(Wq, Wk, Wv, Wo, wq, wk, wv, wo);

    cudaFuncSetAttribute(gemm_qkv, cudaFuncAttributeMaxDynamicSharedMemorySize,
                         GEMM_SMEM);
    cudaFuncSetAttribute(gemm_out, cudaFuncAttributeMaxDynamicSharedMemorySize,
                         GEMM_SMEM);
    gemm_qkv<<<dim3(D_EMB / BN, T_SEQ / BM, 3), 128, GEMM_SMEM>>>(xf, wq, wk, wv,
                                                                  qf, kf, vf);

    cudaFuncSetAttribute(attn_mma, cudaFuncAttributeMaxDynamicSharedMemorySize,
                         ATTN_SMEM);
    attn_mma<<<dim3(T_SEQ / 128, NHEADS), 128, ATTN_SMEM>>>(qf, kf, vf, rf);

    gemm_out<<<dim3(D_EMB / BN, T_SEQ / BM), 128, GEMM_SMEM>>>(rf, wo, out);
}

// round 15
// speedup vs baseline: 1.1265x; 1.0260x over previous
#include <cuda_runtime.h>
#include <cuda_fp16.h>
#include <stdint.h>
#include <math.h>

#define T_SEQ 2048
#define D_EMB 2048
#define HD    128
#define NHEADS 16
#define QK_SCALE 0.08838834764831843f
#define WSCALE 256.0f
#define INV_WSCALE (1.0f / 256.0f)

// ---------------- scratch (no allocs allowed) ----------------
__device__ __half g_Xf[T_SEQ * D_EMB];
__device__ __half g_Rf[T_SEQ * D_EMB];
// weights in NATURAL layout (x256, fp16): Wq/Wk/Wv = [n][k][j], Wo = [k][j]
__device__ __half g_Wq[D_EMB * D_EMB];
__device__ __half g_Wk[D_EMB * D_EMB];
__device__ __half g_Wv[D_EMB * D_EMB];
__device__ __half g_Wo[D_EMB * D_EMB];
__device__ __half g_Qf[T_SEQ * D_EMB];
__device__ __half g_Kf[T_SEQ * D_EMB];
__device__ __half g_Vf[T_SEQ * D_EMB];

// ---------------- PTX helpers (base sm_103-legal only) ----------------
__device__ __forceinline__ uint32_t smem_u32(const void* p) {
    uint32_t a;
    asm("{ .reg .u64 t; cvta.to.shared.u64 t, %1; cvt.u32.u64 %0, t; }"
        : "=r"(a) : "l"(p));
    return a;
}
#define CP_ASYNC16(dst, src) \
    asm volatile("cp.async.cg.shared.global [%0], [%1], 16;" :: "r"(dst), "l"(src))
#define CP_COMMIT() asm volatile("cp.async.commit_group;" ::: "memory")
#define CP_WAIT(n) asm volatile("cp.async.wait_group %0;" :: "n"(n) : "memory")

__device__ __forceinline__ void ldsm_x4(uint32_t& r0, uint32_t& r1, uint32_t& r2,
                                        uint32_t& r3, uint32_t addr) {
    asm volatile("ldmatrix.sync.aligned.m8n8.x4.shared.b16 {%0,%1,%2,%3}, [%4];"
                 : "=r"(r0), "=r"(r1), "=r"(r2), "=r"(r3) : "r"(addr));
}
__device__ __forceinline__ void ldsm_x4_t(uint32_t& r0, uint32_t& r1, uint32_t& r2,
                                          uint32_t& r3, uint32_t addr) {
    asm volatile(
        "ldmatrix.sync.aligned.m8n8.x4.trans.shared.b16 {%0,%1,%2,%3}, [%4];"
        : "=r"(r0), "=r"(r1), "=r"(r2), "=r"(r3) : "r"(addr));
}
__device__ __forceinline__ void mma16816(float* c, const uint32_t* a,
                                         const uint32_t* b) {
    asm volatile(
        "mma.sync.aligned.m16n8k16.row.col.f32.f16.f16.f32 "
        "{%0,%1,%2,%3}, {%4,%5,%6,%7}, {%8,%9}, {%0,%1,%2,%3};"
        : "+f"(c[0]), "+f"(c[1]), "+f"(c[2]), "+f"(c[3])
        : "r"(a[0]), "r"(a[1]), "r"(a[2]), "r"(a[3]), "r"(b[0]), "r"(b[1]));
}
__device__ __forceinline__ uint32_t pack_f16(float x, float y) {
    __half2 h = __floats2half2_rn(x, y);
    return *reinterpret_cast<uint32_t*>(&h);
}

// ---------------- conversion kernels (pure streaming) ----------------
__global__ __launch_bounds__(256) void convX(const float* __restrict__ A,
                                             __half* __restrict__ F) {
    const int i = blockIdx.x * 256 + threadIdx.x;
    float4 v = reinterpret_cast<const float4*>(A)[i];
    __half f[4] = {__float2half_rn(v.x), __float2half_rn(v.y),
                   __float2half_rn(v.z), __float2half_rn(v.w)};
    reinterpret_cast<uint2*>(F)[i] = *reinterpret_cast<uint2*>(f);
}

__global__ __launch_bounds__(256) void convWflat(
    const float* __restrict__ Wq, const float* __restrict__ Wk,
    const float* __restrict__ Wv, const float* __restrict__ Wo,
    __half* __restrict__ Hq, __half* __restrict__ Hk,
    __half* __restrict__ Hv, __half* __restrict__ Ho) {
    const int z = blockIdx.y;
    const float* W = (z == 0) ? Wq : (z == 1) ? Wk : (z == 2) ? Wv : Wo;
    __half* H = (z == 0) ? Hq : (z == 1) ? Hk : (z == 2) ? Hv : Ho;
    const int i = blockIdx.x * 256 + threadIdx.x;
    float4 v = reinterpret_cast<const float4*>(W)[i];
    __half f[4] = {__float2half_rn(v.x * WSCALE), __float2half_rn(v.y * WSCALE),
                   __float2half_rn(v.z * WSCALE), __float2half_rn(v.w * WSCALE)};
    reinterpret_cast<uint2*>(H)[i] = *reinterpret_cast<uint2*>(f);
}

// ---------------- 1-pass fp16 HMMA GEMM (6-stage deep pipeline) --------------
// CTA 128x128, BK=32, 128 threads (2x2 warps of 64x64), 2 CTAs/SM.
// Stage 16KB: A [128m][32k] 64B rows / B [32k][128n] 256B rows (natural layout).
#define BM 128
#define BN 128
#define BK 32
#define STAGE_B 16384
#define NSTAGE 6
#define GEMM_SMEM (NSTAGE * STAGE_B)

__device__ __forceinline__ uint32_t swzA(uint32_t base, int row, int chunk) {
    return base + (((row << 2) + (chunk ^ ((row >> 1) & 3))) << 4);
}
__device__ __forceinline__ uint32_t swzB(uint32_t base, int row, int chunk) {
    return base + (((row << 4) + (chunk ^ (row & 7))) << 4);
}

__device__ __forceinline__ void stage_all(uint32_t sbase, const __half* Af,
                                          const __half* Bp, int bstride, int bm,
                                          int k0, int tid) {
    // A: 128 rows x 4 chunks
#pragma unroll
    for (int u = tid; u < 512; u += 128) {
        const int row = u >> 2, ch = u & 3;
        CP_ASYNC16(swzA(sbase, row, ch),
                   Af + (size_t)(bm + row) * D_EMB + k0 + ch * 8);
    }
    // B: 32 k-rows x 16 chunks (natural [k][n])
#pragma unroll
    for (int u = tid; u < 512; u += 128) {
        const int row = u >> 4, ch = u & 15;
        CP_ASYNC16(swzB(sbase + 8192, row, ch),
                   Bp + (size_t)(k0 + row) * bstride + ch * 8);
    }
}

__device__ __forceinline__ void gemm_core1(
    uint32_t sb, const __half* Af, const __half* Bp, int bstride, int bm,
    int tid, float acc[4][8][4]) {
    const int lane = tid & 31;
    const int wid = tid >> 5;
    const int wm = wid & 1;
    const int wn = wid >> 1;
    const int lr = lane & 7;
    const int lg = lane >> 3;

#pragma unroll
    for (int mt = 0; mt < 4; mt++)
#pragma unroll
        for (int nt = 0; nt < 8; nt++)
#pragma unroll
            for (int e = 0; e < 4; e++) acc[mt][nt][e] = 0.0f;

    const int NITER = D_EMB / BK;  // 64
    // prologue: stages 0..4 (5 chunks in flight)
#pragma unroll
    for (int s = 0; s < NSTAGE - 1; s++) {
        stage_all(sb + s * STAGE_B, Af, Bp, bstride, bm, s * BK, tid);
        CP_COMMIT();
    }

    for (int c = 0; c < NITER; c++) {
        CP_WAIT(4);       // chunks <= c complete (4 newest groups may pend)
        __syncthreads();  // visibility + everyone done reading chunk c-1
        // stage chunk c+5 into slot (c+5)%NSTAGE (held chunk c-1); empty commit at tail
        if (c + NSTAGE - 1 < NITER)
            stage_all(sb + ((c + NSTAGE - 1) % NSTAGE) * STAGE_B, Af, Bp,
                      bstride, bm, (c + NSTAGE - 1) * BK, tid);
        CP_COMMIT();

        const uint32_t sX = sb + (c % NSTAGE) * STAGE_B;
        const uint32_t sB = sX + 8192;

#pragma unroll
        for (int kk = 0; kk < 2; kk++) {
            uint32_t a4[4][4];
#pragma unroll
            for (int mt = 0; mt < 4; mt++) {
                const int row = wm * 64 + mt * 16 + lr + (lg & 1) * 8;
                const int ch = kk * 2 + (lg >> 1);
                ldsm_x4(a4[mt][0], a4[mt][1], a4[mt][2], a4[mt][3],
                        swzA(sX, row, ch));
            }
            uint32_t b4[8][2];
#pragma unroll
            for (int nt = 0; nt < 8; nt += 2) {
                uint32_t v0, v1, v2, v3;
                const int row = kk * 16 + (lg & 1) * 8 + lr;
                const int ch = wn * 8 + nt + (lg >> 1);
                ldsm_x4_t(v0, v1, v2, v3, swzB(sB, row, ch));
                b4[nt][0] = v0;
                b4[nt][1] = v1;
                b4[nt + 1][0] = v2;
                b4[nt + 1][1] = v3;
            }
#pragma unroll
            for (int mt = 0; mt < 4; mt++)
#pragma unroll
                for (int nt = 0; nt < 8; nt++)
                    mma16816(acc[mt][nt], a4[mt], b4[nt]);
        }
    }
    CP_WAIT(0);
    __syncthreads();
}

// fused QKV: z=0 -> Q (scaled); z=1 -> K; z=2 -> V
__global__ __launch_bounds__(128, 2) void gemm_qkv(
    const __half* __restrict__ Xf, const __half* __restrict__ Wq,
    const __half* __restrict__ Wk, const __half* __restrict__ Wv,
    __half* __restrict__ Qf, __half* __restrict__ Kf, __half* __restrict__ Vf) {
    extern __shared__ char sm[];
    const uint32_t sb = smem_u32(sm);
    const int tid = threadIdx.x;
    const int lane = tid & 31;
    const int wid = tid >> 5;
    const int z = blockIdx.z;
    const int bm = blockIdx.y * BM;
    const int bn = blockIdx.x * BN;

    const __half* W = (z == 0) ? Wq : (z == 1) ? Wk : Wv;
    const __half* Bp = W + (size_t)(bn >> 7) * D_EMB * HD;  // BN == HD

    float acc[4][8][4];
    gemm_core1(sb, Xf, Bp, HD, bm, tid, acc);

    const int wm = wid & 1;
    const int wn = wid >> 1;
    __half* Dst = (z == 0) ? Qf : (z == 1) ? Kf : Vf;
    const float s = (z == 0) ? (QK_SCALE * INV_WSCALE) : INV_WSCALE;
#pragma unroll
    for (int mt = 0; mt < 4; mt++) {
        const int row = bm + wm * 64 + mt * 16 + (lane >> 2);
#pragma unroll
        for (int nt = 0; nt < 8; nt++) {
            const int col = bn + wn * 64 + nt * 8 + (lane & 3) * 2;
            *reinterpret_cast<uint32_t*>(&Dst[(size_t)row * D_EMB + col]) =
                pack_f16(acc[mt][nt][0] * s, acc[mt][nt][1] * s);
            *reinterpret_cast<uint32_t*>(&Dst[(size_t)(row + 8) * D_EMB + col]) =
                pack_f16(acc[mt][nt][2] * s, acc[mt][nt][3] * s);
        }
    }
}

// out-projection: fp32 output
__global__ __launch_bounds__(128, 2) void gemm_out(
    const __half* __restrict__ Af, const __half* __restrict__ Wo,
    float* __restrict__ C) {
    extern __shared__ char sm[];
    const uint32_t sb = smem_u32(sm);
    const int tid = threadIdx.x;
    const int lane = tid & 31;
    const int wid = tid >> 5;
    const int bm = blockIdx.y * BM;
    const int bn = blockIdx.x * BN;

    const __half* Bp = Wo + bn;

    float acc[4][8][4];
    gemm_core1(sb, Af, Bp, D_EMB, bm, tid, acc);

    const int wm = wid & 1;
    const int wn = wid >> 1;
#pragma unroll
    for (int mt = 0; mt < 4; mt++) {
        const int row = bm + wm * 64 + mt * 16 + (lane >> 2);
#pragma unroll
        for (int nt = 0; nt < 8; nt++) {
            const int col = bn + wn * 64 + nt * 8 + (lane & 3) * 2;
            *reinterpret_cast<float2*>(&C[(size_t)row * D_EMB + col]) =
                make_float2(acc[mt][nt][0] * INV_WSCALE, acc[mt][nt][1] * INV_WSCALE);
            *reinterpret_cast<float2*>(&C[(size_t)(row + 8) * D_EMB + col]) =
                make_float2(acc[mt][nt][2] * INV_WSCALE, acc[mt][nt][3] * INV_WSCALE);
        }
    }
}

// ---------------- fp16 HMMA flash attention (round-9 config) ----------------
#define ATTN_SMEM 65536

__global__ __launch_bounds__(128, 2) void attn_mma(
    const __half* __restrict__ Qf, const __half* __restrict__ Kf,
    const __half* __restrict__ Vf, __half* __restrict__ Rf) {
    extern __shared__ char sm[];
    const uint32_t sb = smem_u32(sm);
    const uint32_t sQ = sb;
    const uint32_t sK = sb + 32768;
    const uint32_t sV = sb + 49152;

    const int n = blockIdx.y;
    const int m0 = blockIdx.x * 128;
    const int tid = threadIdx.x;
    const int lane = tid & 31;
    const int w = tid >> 5;
    const int lr = lane & 7;
    const int lg = lane >> 3;

    for (int u = tid; u < 2048; u += 128) {
        const int row = u >> 4, ch = u & 15;
        const uint32_t d = (uint32_t)((row * 16 + (ch ^ (row & 7))) * 16);
        CP_ASYNC16(sQ + d, Qf + (size_t)(m0 + row) * D_EMB + n * HD + ch * 8);
    }
    CP_COMMIT();
    for (int u = tid; u < 1024; u += 128) {
        const int row = u >> 4, ch = u & 15;
        const uint32_t d = (uint32_t)((row * 16 + (ch ^ (row & 7))) * 16);
        CP_ASYNC16(sK + d, Kf + (size_t)row * D_EMB + n * HD + ch * 8);
    }
    CP_COMMIT();
    for (int u = tid; u < 1024; u += 128) {
        const int row = u >> 4, ch = u & 15;
        const uint32_t d = (uint32_t)((row * 16 + (ch ^ (row & 7))) * 16);
        CP_ASYNC16(sV + d, Vf + (size_t)row * D_EMB + n * HD + ch * 8);
    }
    CP_COMMIT();

    float acc[2][16][4];
#pragma unroll
    for (int mt = 0; mt < 2; mt++)
#pragma unroll
        for (int ht = 0; ht < 16; ht++)
#pragma unroll
            for (int e = 0; e < 4; e++) acc[mt][ht][e] = 0.0f;
    float M0[2] = {-1e30f, -1e30f}, M1[2] = {-1e30f, -1e30f};
    float L0[2] = {0.0f, 0.0f}, L1[2] = {0.0f, 0.0f};

    const int NT = T_SEQ / 64;
    for (int it = 0; it < NT; it++) {
        CP_WAIT(1);
        __syncthreads();

        float c[2][8][4];
#pragma unroll
        for (int mt = 0; mt < 2; mt++)
#pragma unroll
            for (int t = 0; t < 8; t++)
#pragma unroll
                for (int e = 0; e < 4; e++) c[mt][t][e] = 0.0f;

#pragma unroll
        for (int kk = 0; kk < 8; kk++) {
            uint32_t q4[2][4];
#pragma unroll
            for (int mt = 0; mt < 2; mt++) {
                const int row = w * 32 + mt * 16 + lr + (lg & 1) * 8;
                const int ch = kk * 2 + (lg >> 1);
                const uint32_t a = (uint32_t)((row * 16 + (ch ^ (row & 7))) * 16);
                ldsm_x4(q4[mt][0], q4[mt][1], q4[mt][2], q4[mt][3], sQ + a);
            }
#pragma unroll
            for (int np = 0; np < 4; np++) {
                uint32_t k4[4];
                const int row = np * 16 + lr + (lg >> 1) * 8;
                const int ch = kk * 2 + (lg & 1);
                const uint32_t a = (uint32_t)((row * 16 + (ch ^ (row & 7))) * 16);
                ldsm_x4(k4[0], k4[1], k4[2], k4[3], sK + a);
#pragma unroll
                for (int mt = 0; mt < 2; mt++) {
                    mma16816(c[mt][np * 2],     q4[mt], &k4[0]);
                    mma16816(c[mt][np * 2 + 1], q4[mt], &k4[2]);
                }
            }
        }
        __syncthreads();

        if (it + 1 < NT) {
            for (int u = tid; u < 1024; u += 128) {
                const int row = u >> 4, ch = u & 15;
                const uint32_t d = (uint32_t)((row * 16 + (ch ^ (row & 7))) * 16);
                CP_ASYNC16(sK + d, Kf + (size_t)((it + 1) * 64 + row) * D_EMB +
                                       n * HD + ch * 8);
            }
            CP_COMMIT();
        }

#pragma unroll
        for (int mt = 0; mt < 2; mt++) {
            float mx0 = -1e30f, mx1 = -1e30f;
#pragma unroll
            for (int t = 0; t < 8; t++) {
                mx0 = fmaxf(mx0, fmaxf(c[mt][t][0], c[mt][t][1]));
                mx1 = fmaxf(mx1, fmaxf(c[mt][t][2], c[mt][t][3]));
            }
            mx0 = fmaxf(mx0, __shfl_xor_sync(0xffffffffu, mx0, 1));
            mx0 = fmaxf(mx0, __shfl_xor_sync(0xffffffffu, mx0, 2));
            mx1 = fmaxf(mx1, __shfl_xor_sync(0xffffffffu, mx1, 1));
            mx1 = fmaxf(mx1, __shfl_xor_sync(0xffffffffu, mx1, 2));

            const float Mn0 = fmaxf(M0[mt], mx0), Mn1 = fmaxf(M1[mt], mx1);
            const float a0 = __expf(M0[mt] - Mn0), a1 = __expf(M1[mt] - Mn1);
            float sum0 = 0.0f, sum1 = 0.0f;
#pragma unroll
            for (int t = 0; t < 8; t++) {
                c[mt][t][0] = __expf(c[mt][t][0] - Mn0);
                c[mt][t][1] = __expf(c[mt][t][1] - Mn0);
                c[mt][t][2] = __expf(c[mt][t][2] - Mn1);
                c[mt][t][3] = __expf(c[mt][t][3] - Mn1);
                sum0 += c[mt][t][0] + c[mt][t][1];
                sum1 += c[mt][t][2] + c[mt][t][3];
            }
            sum0 += __shfl_xor_sync(0xffffffffu, sum0, 1);
            sum0 += __shfl_xor_sync(0xffffffffu, sum0, 2);
            sum1 += __shfl_xor_sync(0xffffffffu, sum1, 1);
            sum1 += __shfl_xor_sync(0xffffffffu, sum1, 2);
            L0[mt] = L0[mt] * a0 + sum0;
            L1[mt] = L1[mt] * a1 + sum1;
            M0[mt] = Mn0;
            M1[mt] = Mn1;
#pragma unroll
            for (int ht = 0; ht < 16; ht++) {
                acc[mt][ht][0] *= a0;
                acc[mt][ht][1] *= a0;
                acc[mt][ht][2] *= a1;
                acc[mt][ht][3] *= a1;
            }
        }

        if (it + 1 < NT) {
            CP_WAIT(1);
        } else {
            CP_WAIT(0);
        }
        __syncthreads();

#pragma unroll
        for (int kk = 0; kk < 4; kk++) {
            uint32_t ap[2][4];
#pragma unroll
            for (int mt = 0; mt < 2; mt++) {
                const int t0 = kk * 2, t1 = kk * 2 + 1;
                ap[mt][0] = pack_f16(c[mt][t0][0], c[mt][t0][1]);
                ap[mt][1] = pack_f16(c[mt][t0][2], c[mt][t0][3]);
                ap[mt][2] = pack_f16(c[mt][t1][0], c[mt][t1][1]);
                ap[mt][3] = pack_f16(c[mt][t1][2], c[mt][t1][3]);
            }
#pragma unroll
            for (int hq = 0; hq < 8; hq++) {
                uint32_t v4[4];
                const int row = kk * 16 + (lg & 1) * 8 + lr;
                const int ch = hq * 2 + (lg >> 1);
                const uint32_t a = (uint32_t)((row * 16 + (ch ^ (row & 7))) * 16);
                ldsm_x4_t(v4[0], v4[1], v4[2], v4[3], sV + a);
#pragma unroll
                for (int mt = 0; mt < 2; mt++) {
                    mma16816(acc[mt][hq * 2],     ap[mt], &v4[0]);
                    mma16816(acc[mt][hq * 2 + 1], ap[mt], &v4[2]);
                }
            }
        }
        __syncthreads();

        if (it + 1 < NT) {
            for (int u = tid; u < 1024; u += 128) {
                const int row = u >> 4, ch = u & 15;
                const uint32_t d = (uint32_t)((row * 16 + (ch ^ (row & 7))) * 16);
                CP_ASYNC16(sV + d, Vf + (size_t)((it + 1) * 64 + row) * D_EMB +
                                       n * HD + ch * 8);
            }
            CP_COMMIT();
        }
    }

#pragma unroll
    for (int mt = 0; mt < 2; mt++) {
        const float i0 = 1.0f / L0[mt], i1 = 1.0f / L1[mt];
        const int rowg = m0 + w * 32 + mt * 16 + (lane >> 2);
#pragma unroll
        for (int ht = 0; ht < 16; ht++) {
            const int col = n * HD + ht * 8 + (lane & 3) * 2;
            *reinterpret_cast<uint32_t*>(&Rf[(size_t)rowg * D_EMB + col]) =
                pack_f16(acc[mt][ht][0] * i0, acc[mt][ht][1] * i0);
            *reinterpret_cast<uint32_t*>(&Rf[(size_t)(rowg + 8) * D_EMB + col]) =
                pack_f16(acc[mt][ht][2] * i1, acc[mt][ht][3] * i1);
        }
    }
}

// ---------------------------------------------------------------------------
extern "C" void kernel_launch(void* const* d_in, const int* in_sizes, int n_in,
                              void* d_out, int out_size) {
    const float* X  = (const float*)d_in[0];
    const float* Wq = (const float*)d_in[1];
    const float* Wk = (const float*)d_in[2];
    const float* Wv = (const float*)d_in[3];
    const float* Wo = (const float*)d_in[4];
    float* out = (float*)d_out;

    __half *xf, *rf, *qf, *kf, *vf, *wq, *wk, *wv, *wo;
    cudaGetSymbolAddress((void**)&xf, g_Xf);
    cudaGetSymbolAddress((void**)&rf, g_Rf);
    cudaGetSymbolAddress((void**)&qf, g_Qf);
    cudaGetSymbolAddress((void**)&kf, g_Kf);
    cudaGetSymbolAddress((void**)&vf, g_Vf);
    cudaGetSymbolAddress((void**)&wq, g_Wq);
    cudaGetSymbolAddress((void**)&wk, g_Wk);
    cudaGetSymbolAddress((void**)&wv, g_Wv);
    cudaGetSymbolAddress((void**)&wo, g_Wo);

    const int NELE4 = T_SEQ * D_EMB / 4 / 256;

    convX<<<NELE4, 256>>>(X, xf);
    convWflat<<<dim3(NELE4, 4), 256>>>(Wq, Wk, Wv, Wo, wq, wk, wv, wo);

    cudaFuncSetAttribute(gemm_qkv, cudaFuncAttributeMaxDynamicSharedMemorySize,
                         GEMM_SMEM);
    cudaFuncSetAttribute(gemm_out, cudaFuncAttributeMaxDynamicSharedMemorySize,
                         GEMM_SMEM);
    gemm_qkv<<<dim3(D_EMB / BN, T_SEQ / BM, 3), 128, GEMM_SMEM>>>(xf, wq, wk, wv,
                                                                  qf, kf, vf);

    cudaFuncSetAttribute(attn_mma, cudaFuncAttributeMaxDynamicSharedMemorySize,
                         ATTN_SMEM);
    attn_mma<<<dim3(T_SEQ / 128, NHEADS), 128, ATTN_SMEM>>>(qf, kf, vf, rf);

    gemm_out<<<dim3(D_EMB / BN, T_SEQ / BM), 128, GEMM_SMEM>>>(rf, wo, out);
}

// round 16
// speedup vs baseline: 1.1450x; 1.0164x over previous
#include <cuda_runtime.h>
#include <cuda_fp16.h>
#include <stdint.h>
#include <math.h>

#define T_SEQ 2048
#define D_EMB 2048
#define HD    128
#define NHEADS 16
// Q scale folded with log2(e): softmax computed in base-2 units.
#define QK_SCALE2 0.12753138106334646f  // (1/sqrt(128)) * log2(e)
#define WSCALE 256.0f
#define INV_WSCALE (1.0f / 256.0f)

// ---------------- scratch (no allocs allowed) ----------------
__device__ __half g_Xf[T_SEQ * D_EMB];
__device__ __half g_Rf[T_SEQ * D_EMB];
// weights in NATURAL layout (x256, fp16): Wq/Wk/Wv = [n][k][j], Wo = [k][j]
__device__ __half g_Wq[D_EMB * D_EMB];
__device__ __half g_Wk[D_EMB * D_EMB];
__device__ __half g_Wv[D_EMB * D_EMB];
__device__ __half g_Wo[D_EMB * D_EMB];
__device__ __half g_Qf[T_SEQ * D_EMB];
__device__ __half g_Kf[T_SEQ * D_EMB];
__device__ __half g_Vf[T_SEQ * D_EMB];

// ---------------- PTX helpers (base sm_103-legal only) ----------------
__device__ __forceinline__ uint32_t smem_u32(const void* p) {
    uint32_t a;
    asm("{ .reg .u64 t; cvta.to.shared.u64 t, %1; cvt.u32.u64 %0, t; }"
        : "=r"(a) : "l"(p));
    return a;
}
#define CP_ASYNC16(dst, src) \
    asm volatile("cp.async.cg.shared.global [%0], [%1], 16;" :: "r"(dst), "l"(src))
#define CP_COMMIT() asm volatile("cp.async.commit_group;" ::: "memory")
#define CP_WAIT(n) asm volatile("cp.async.wait_group %0;" :: "n"(n) : "memory")

__device__ __forceinline__ void ldsm_x4(uint32_t& r0, uint32_t& r1, uint32_t& r2,
                                        uint32_t& r3, uint32_t addr) {
    asm volatile("ldmatrix.sync.aligned.m8n8.x4.shared.b16 {%0,%1,%2,%3}, [%4];"
                 : "=r"(r0), "=r"(r1), "=r"(r2), "=r"(r3) : "r"(addr));
}
__device__ __forceinline__ void ldsm_x4_t(uint32_t& r0, uint32_t& r1, uint32_t& r2,
                                          uint32_t& r3, uint32_t addr) {
    asm volatile(
        "ldmatrix.sync.aligned.m8n8.x4.trans.shared.b16 {%0,%1,%2,%3}, [%4];"
        : "=r"(r0), "=r"(r1), "=r"(r2), "=r"(r3) : "r"(addr));
}
__device__ __forceinline__ void mma16816(float* c, const uint32_t* a,
                                         const uint32_t* b) {
    asm volatile(
        "mma.sync.aligned.m16n8k16.row.col.f32.f16.f16.f32 "
        "{%0,%1,%2,%3}, {%4,%5,%6,%7}, {%8,%9}, {%0,%1,%2,%3};"
        : "+f"(c[0]), "+f"(c[1]), "+f"(c[2]), "+f"(c[3])
        : "r"(a[0]), "r"(a[1]), "r"(a[2]), "r"(a[3]), "r"(b[0]), "r"(b[1]));
}
__device__ __forceinline__ uint32_t pack_f16(float x, float y) {
    __half2 h = __floats2half2_rn(x, y);
    return *reinterpret_cast<uint32_t*>(&h);
}

// ---------------- merged conversion kernel (pure streaming) ----------------
// z=0: X (scale 1); z=1..4: Wq/Wk/Wv/Wo (scale WSCALE). Natural layouts.
__global__ __launch_bounds__(256) void convAll(
    const float* __restrict__ X, const float* __restrict__ Wq,
    const float* __restrict__ Wk, const float* __restrict__ Wv,
    const float* __restrict__ Wo, __half* __restrict__ Xh,
    __half* __restrict__ Hq, __half* __restrict__ Hk,
    __half* __restrict__ Hv, __half* __restrict__ Ho) {
    const int z = blockIdx.y;
    const float* S = (z == 0) ? X : (z == 1) ? Wq : (z == 2) ? Wk
                     : (z == 3) ? Wv : Wo;
    __half* D = (z == 0) ? Xh : (z == 1) ? Hq : (z == 2) ? Hk
                : (z == 3) ? Hv : Ho;
    const float sc = (z == 0) ? 1.0f : WSCALE;
    const int i = blockIdx.x * 256 + threadIdx.x;
    float4 v = reinterpret_cast<const float4*>(S)[i];
    __half f[4] = {__float2half_rn(v.x * sc), __float2half_rn(v.y * sc),
                   __float2half_rn(v.z * sc), __float2half_rn(v.w * sc)};
    reinterpret_cast<uint2*>(D)[i] = *reinterpret_cast<uint2*>(f);
}

// ---------------- 1-pass fp16 HMMA GEMM (6-stage deep pipeline) --------------
#define BM 128
#define BN 128
#define BK 32
#define STAGE_B 16384
#define NSTAGE 6
#define GEMM_SMEM (NSTAGE * STAGE_B)

__device__ __forceinline__ uint32_t swzA(uint32_t base, int row, int chunk) {
    return base + (((row << 2) + (chunk ^ ((row >> 1) & 3))) << 4);
}
__device__ __forceinline__ uint32_t swzB(uint32_t base, int row, int chunk) {
    return base + (((row << 4) + (chunk ^ (row & 7))) << 4);
}

__device__ __forceinline__ void stage_all(uint32_t sbase, const __half* Af,
                                          const __half* Bp, int bstride, int bm,
                                          int k0, int tid) {
#pragma unroll
    for (int u = tid; u < 512; u += 128) {
        const int row = u >> 2, ch = u & 3;
        CP_ASYNC16(swzA(sbase, row, ch),
                   Af + (size_t)(bm + row) * D_EMB + k0 + ch * 8);
    }
#pragma unroll
    for (int u = tid; u < 512; u += 128) {
        const int row = u >> 4, ch = u & 15;
        CP_ASYNC16(swzB(sbase + 8192, row, ch),
                   Bp + (size_t)(k0 + row) * bstride + ch * 8);
    }
}

__device__ __forceinline__ void gemm_core1(
    uint32_t sb, const __half* Af, const __half* Bp, int bstride, int bm,
    int tid, float acc[4][8][4]) {
    const int lane = tid & 31;
    const int wid = tid >> 5;
    const int wm = wid & 1;
    const int wn = wid >> 1;
    const int lr = lane & 7;
    const int lg = lane >> 3;

#pragma unroll
    for (int mt = 0; mt < 4; mt++)
#pragma unroll
        for (int nt = 0; nt < 8; nt++)
#pragma unroll
            for (int e = 0; e < 4; e++) acc[mt][nt][e] = 0.0f;

    const int NITER = D_EMB / BK;  // 64
#pragma unroll
    for (int s = 0; s < NSTAGE - 1; s++) {
        stage_all(sb + s * STAGE_B, Af, Bp, bstride, bm, s * BK, tid);
        CP_COMMIT();
    }

    for (int c = 0; c < NITER; c++) {
        CP_WAIT(4);
        __syncthreads();
        if (c + NSTAGE - 1 < NITER)
            stage_all(sb + ((c + NSTAGE - 1) % NSTAGE) * STAGE_B, Af, Bp,
                      bstride, bm, (c + NSTAGE - 1) * BK, tid);
        CP_COMMIT();

        const uint32_t sX = sb + (c % NSTAGE) * STAGE_B;
        const uint32_t sB = sX + 8192;

#pragma unroll
        for (int kk = 0; kk < 2; kk++) {
            uint32_t a4[4][4];
#pragma unroll
            for (int mt = 0; mt < 4; mt++) {
                const int row = wm * 64 + mt * 16 + lr + (lg & 1) * 8;
                const int ch = kk * 2 + (lg >> 1);
                ldsm_x4(a4[mt][0], a4[mt][1], a4[mt][2], a4[mt][3],
                        swzA(sX, row, ch));
            }
            uint32_t b4[8][2];
#pragma unroll
            for (int nt = 0; nt < 8; nt += 2) {
                uint32_t v0, v1, v2, v3;
                const int row = kk * 16 + (lg & 1) * 8 + lr;
                const int ch = wn * 8 + nt + (lg >> 1);
                ldsm_x4_t(v0, v1, v2, v3, swzB(sB, row, ch));
                b4[nt][0] = v0;
                b4[nt][1] = v1;
                b4[nt + 1][0] = v2;
                b4[nt + 1][1] = v3;
            }
#pragma unroll
            for (int mt = 0; mt < 4; mt++)
#pragma unroll
                for (int nt = 0; nt < 8; nt++)
                    mma16816(acc[mt][nt], a4[mt], b4[nt]);
        }
    }
    CP_WAIT(0);
    __syncthreads();
}

// fused QKV: z=0 -> Q (scaled by QK_SCALE2); z=1 -> K; z=2 -> V
__global__ __launch_bounds__(128, 2) void gemm_qkv(
    const __half* __restrict__ Xf, const __half* __restrict__ Wq,
    const __half* __restrict__ Wk, const __half* __restrict__ Wv,
    __half* __restrict__ Qf, __half* __restrict__ Kf, __half* __restrict__ Vf) {
    extern __shared__ char sm[];
    const uint32_t sb = smem_u32(sm);
    const int tid = threadIdx.x;
    const int lane = tid & 31;
    const int wid = tid >> 5;
    const int z = blockIdx.z;
    const int bm = blockIdx.y * BM;
    const int bn = blockIdx.x * BN;

    const __half* W = (z == 0) ? Wq : (z == 1) ? Wk : Wv;
    const __half* Bp = W + (size_t)(bn >> 7) * D_EMB * HD;  // BN == HD

    float acc[4][8][4];
    gemm_core1(sb, Xf, Bp, HD, bm, tid, acc);

    const int wm = wid & 1;
    const int wn = wid >> 1;
    __half* Dst = (z == 0) ? Qf : (z == 1) ? Kf : Vf;
    const float s = (z == 0) ? (QK_SCALE2 * INV_WSCALE) : INV_WSCALE;
#pragma unroll
    for (int mt = 0; mt < 4; mt++) {
        const int row = bm + wm * 64 + mt * 16 + (lane >> 2);
#pragma unroll
        for (int nt = 0; nt < 8; nt++) {
            const int col = bn + wn * 64 + nt * 8 + (lane & 3) * 2;
            *reinterpret_cast<uint32_t*>(&Dst[(size_t)row * D_EMB + col]) =
                pack_f16(acc[mt][nt][0] * s, acc[mt][nt][1] * s);
            *reinterpret_cast<uint32_t*>(&Dst[(size_t)(row + 8) * D_EMB + col]) =
                pack_f16(acc[mt][nt][2] * s, acc[mt][nt][3] * s);
        }
    }
}

// out-projection: fp32 output
__global__ __launch_bounds__(128, 2) void gemm_out(
    const __half* __restrict__ Af, const __half* __restrict__ Wo,
    float* __restrict__ C) {
    extern __shared__ char sm[];
    const uint32_t sb = smem_u32(sm);
    const int tid = threadIdx.x;
    const int lane = tid & 31;
    const int wid = tid >> 5;
    const int bm = blockIdx.y * BM;
    const int bn = blockIdx.x * BN;

    const __half* Bp = Wo + bn;

    float acc[4][8][4];
    gemm_core1(sb, Af, Bp, D_EMB, bm, tid, acc);

    const int wm = wid & 1;
    const int wn = wid >> 1;
#pragma unroll
    for (int mt = 0; mt < 4; mt++) {
        const int row = bm + wm * 64 + mt * 16 + (lane >> 2);
#pragma unroll
        for (int nt = 0; nt < 8; nt++) {
            const int col = bn + wn * 64 + nt * 8 + (lane & 3) * 2;
            *reinterpret_cast<float2*>(&C[(size_t)row * D_EMB + col]) =
                make_float2(acc[mt][nt][0] * INV_WSCALE, acc[mt][nt][1] * INV_WSCALE);
            *reinterpret_cast<float2*>(&C[(size_t)(row + 8) * D_EMB + col]) =
                make_float2(acc[mt][nt][2] * INV_WSCALE, acc[mt][nt][3] * INV_WSCALE);
        }
    }
}

// ---------------- fp16 HMMA flash attention (base-2 softmax) ----------------
#define ATTN_SMEM 65536

__global__ __launch_bounds__(128, 2) void attn_mma(
    const __half* __restrict__ Qf, const __half* __restrict__ Kf,
    const __half* __restrict__ Vf, __half* __restrict__ Rf) {
    extern __shared__ char sm[];
    const uint32_t sb = smem_u32(sm);
    const uint32_t sQ = sb;
    const uint32_t sK = sb + 32768;
    const uint32_t sV = sb + 49152;

    const int n = blockIdx.y;
    const int m0 = blockIdx.x * 128;
    const int tid = threadIdx.x;
    const int lane = tid & 31;
    const int w = tid >> 5;
    const int lr = lane & 7;
    const int lg = lane >> 3;

    for (int u = tid; u < 2048; u += 128) {
        const int row = u >> 4, ch = u & 15;
        const uint32_t d = (uint32_t)((row * 16 + (ch ^ (row & 7))) * 16);
        CP_ASYNC16(sQ + d, Qf + (size_t)(m0 + row) * D_EMB + n * HD + ch * 8);
    }
    CP_COMMIT();
    for (int u = tid; u < 1024; u += 128) {
        const int row = u >> 4, ch = u & 15;
        const uint32_t d = (uint32_t)((row * 16 + (ch ^ (row & 7))) * 16);
        CP_ASYNC16(sK + d, Kf + (size_t)row * D_EMB + n * HD + ch * 8);
    }
    CP_COMMIT();
    for (int u = tid; u < 1024; u += 128) {
        const int row = u >> 4, ch = u & 15;
        const uint32_t d = (uint32_t)((row * 16 + (ch ^ (row & 7))) * 16);
        CP_ASYNC16(sV + d, Vf + (size_t)row * D_EMB + n * HD + ch * 8);
    }
    CP_COMMIT();

    float acc[2][16][4];
#pragma unroll
    for (int mt = 0; mt < 2; mt++)
#pragma unroll
        for (int ht = 0; ht < 16; ht++)
#pragma unroll
            for (int e = 0; e < 4; e++) acc[mt][ht][e] = 0.0f;
    float M0[2] = {-1e30f, -1e30f}, M1[2] = {-1e30f, -1e30f};
    float L0[2] = {0.0f, 0.0f}, L1[2] = {0.0f, 0.0f};

    const int NT = T_SEQ / 64;
    for (int it = 0; it < NT; it++) {
        CP_WAIT(1);
        __syncthreads();

        float c[2][8][4];
#pragma unroll
        for (int mt = 0; mt < 2; mt++)
#pragma unroll
            for (int t = 0; t < 8; t++)
#pragma unroll
                for (int e = 0; e < 4; e++) c[mt][t][e] = 0.0f;

#pragma unroll
        for (int kk = 0; kk < 8; kk++) {
            uint32_t q4[2][4];
#pragma unroll
            for (int mt = 0; mt < 2; mt++) {
                const int row = w * 32 + mt * 16 + lr + (lg & 1) * 8;
                const int ch = kk * 2 + (lg >> 1);
                const uint32_t a = (uint32_t)((row * 16 + (ch ^ (row & 7))) * 16);
                ldsm_x4(q4[mt][0], q4[mt][1], q4[mt][2], q4[mt][3], sQ + a);
            }
#pragma unroll
            for (int np = 0; np < 4; np++) {
                uint32_t k4[4];
                const int row = np * 16 + lr + (lg >> 1) * 8;
                const int ch = kk * 2 + (lg & 1);
                const uint32_t a = (uint32_t)((row * 16 + (ch ^ (row & 7))) * 16);
                ldsm_x4(k4[0], k4[1], k4[2], k4[3], sK + a);
#pragma unroll
                for (int mt = 0; mt < 2; mt++) {
                    mma16816(c[mt][np * 2],     q4[mt], &k4[0]);
                    mma16816(c[mt][np * 2 + 1], q4[mt], &k4[2]);
                }
            }
        }
        __syncthreads();

        if (it + 1 < NT) {
            for (int u = tid; u < 1024; u += 128) {
                const int row = u >> 4, ch = u & 15;
                const uint32_t d = (uint32_t)((row * 16 + (ch ^ (row & 7))) * 16);
                CP_ASYNC16(sK + d, Kf + (size_t)((it + 1) * 64 + row) * D_EMB +
                                       n * HD + ch * 8);
            }
            CP_COMMIT();
        }

        // ---- online softmax in base-2 units (exp2f, no log2e multiplies) ----
#pragma unroll
        for (int mt = 0; mt < 2; mt++) {
            float mx0 = -1e30f, mx1 = -1e30f;
#pragma unroll
            for (int t = 0; t < 8; t++) {
                mx0 = fmaxf(mx0, fmaxf(c[mt][t][0], c[mt][t][1]));
                mx1 = fmaxf(mx1, fmaxf(c[mt][t][2], c[mt][t][3]));
            }
            mx0 = fmaxf(mx0, __shfl_xor_sync(0xffffffffu, mx0, 1));
            mx0 = fmaxf(mx0, __shfl_xor_sync(0xffffffffu, mx0, 2));
            mx1 = fmaxf(mx1, __shfl_xor_sync(0xffffffffu, mx1, 1));
            mx1 = fmaxf(mx1, __shfl_xor_sync(0xffffffffu, mx1, 2));

            const float Mn0 = fmaxf(M0[mt], mx0), Mn1 = fmaxf(M1[mt], mx1);
            const float a0 = exp2f(M0[mt] - Mn0), a1 = exp2f(M1[mt] - Mn1);
            float sum0 = 0.0f, sum1 = 0.0f;
#pragma unroll
            for (int t = 0; t < 8; t++) {
                c[mt][t][0] = exp2f(c[mt][t][0] - Mn0);
                c[mt][t][1] = exp2f(c[mt][t][1] - Mn0);
                c[mt][t][2] = exp2f(c[mt][t][2] - Mn1);
                c[mt][t][3] = exp2f(c[mt][t][3] - Mn1);
                sum0 += c[mt][t][0] + c[mt][t][1];
                sum1 += c[mt][t][2] + c[mt][t][3];
            }
            sum0 += __shfl_xor_sync(0xffffffffu, sum0, 1);
            sum0 += __shfl_xor_sync(0xffffffffu, sum0, 2);
            sum1 += __shfl_xor_sync(0xffffffffu, sum1, 1);
            sum1 += __shfl_xor_sync(0xffffffffu, sum1, 2);
            L0[mt] = L0[mt] * a0 + sum0;
            L1[mt] = L1[mt] * a1 + sum1;
            M0[mt] = Mn0;
            M1[mt] = Mn1;
#pragma unroll
            for (int ht = 0; ht < 16; ht++) {
                acc[mt][ht][0] *= a0;
                acc[mt][ht][1] *= a0;
                acc[mt][ht][2] *= a1;
                acc[mt][ht][3] *= a1;
            }
        }

        if (it + 1 < NT) {
            CP_WAIT(1);
        } else {
            CP_WAIT(0);
        }
        __syncthreads();

#pragma unroll
        for (int kk = 0; kk < 4; kk++) {
            uint32_t ap[2][4];
#pragma unroll
            for (int mt = 0; mt < 2; mt++) {
                const int t0 = kk * 2, t1 = kk * 2 + 1;
                ap[mt][0] = pack_f16(c[mt][t0][0], c[mt][t0][1]);
                ap[mt][1] = pack_f16(c[mt][t0][2], c[mt][t0][3]);
                ap[mt][2] = pack_f16(c[mt][t1][0], c[mt][t1][1]);
                ap[mt][3] = pack_f16(c[mt][t1][2], c[mt][t1][3]);
            }
#pragma unroll
            for (int hq = 0; hq < 8; hq++) {
                uint32_t v4[4];
                const int row = kk * 16 + (lg & 1) * 8 + lr;
                const int ch = hq * 2 + (lg >> 1);
                const uint32_t a = (uint32_t)((row * 16 + (ch ^ (row & 7))) * 16);
                ldsm_x4_t(v4[0], v4[1], v4[2], v4[3], sV + a);
#pragma unroll
                for (int mt = 0; mt < 2; mt++) {
                    mma16816(acc[mt][hq * 2],     ap[mt], &v4[0]);
                    mma16816(acc[mt][hq * 2 + 1], ap[mt], &v4[2]);
                }
            }
        }
        __syncthreads();

        if (it + 1 < NT) {
            for (int u = tid; u < 1024; u += 128) {
                const int row = u >> 4, ch = u & 15;
                const uint32_t d = (uint32_t)((row * 16 + (ch ^ (row & 7))) * 16);
                CP_ASYNC16(sV + d, Vf + (size_t)((it + 1) * 64 + row) * D_EMB +
                                       n * HD + ch * 8);
            }
            CP_COMMIT();
        }
    }

#pragma unroll
    for (int mt = 0; mt < 2; mt++) {
        const float i0 = 1.0f / L0[mt], i1 = 1.0f / L1[mt];
        const int rowg = m0 + w * 32 + mt * 16 + (lane >> 2);
#pragma unroll
        for (int ht = 0; ht < 16; ht++) {
            const int col = n * HD + ht * 8 + (lane & 3) * 2;
            *reinterpret_cast<uint32_t*>(&Rf[(size_t)rowg * D_EMB + col]) =
                pack_f16(acc[mt][ht][0] * i0, acc[mt][ht][1] * i0);
            *reinterpret_cast<uint32_t*>(&Rf[(size_t)(rowg + 8) * D_EMB + col]) =
                pack_f16(acc[mt][ht][2] * i1, acc[mt][ht][3] * i1);
        }
    }
}

// ---------------------------------------------------------------------------
extern "C" void kernel_launch(void* const* d_in, const int* in_sizes, int n_in,
                              void* d_out, int out_size) {
    const float* X  = (const float*)d_in[0];
    const float* Wq = (const float*)d_in[1];
    const float* Wk = (const float*)d_in[2];
    const float* Wv = (const float*)d_in[3];
    const float* Wo = (const float*)d_in[4];
    float* out = (float*)d_out;

    __half *xf, *rf, *qf, *kf, *vf, *wq, *wk, *wv, *wo;
    cudaGetSymbolAddress((void**)&xf, g_Xf);
    cudaGetSymbolAddress((void**)&rf, g_Rf);
    cudaGetSymbolAddress((void**)&qf, g_Qf);
    cudaGetSymbolAddress((void**)&kf, g_Kf);
    cudaGetSymbolAddress((void**)&vf, g_Vf);
    cudaGetSymbolAddress((void**)&wq, g_Wq);
    cudaGetSymbolAddress((void**)&wk, g_Wk);
    cudaGetSymbolAddress((void**)&wv, g_Wv);
    cudaGetSymbolAddress((void**)&wo, g_Wo);

    const int NELE4 = T_SEQ * D_EMB / 4 / 256;

    convAll<<<dim3(NELE4, 5), 256>>>(X, Wq, Wk, Wv, Wo, xf, wq, wk, wv, wo);

    cudaFuncSetAttribute(gemm_qkv, cudaFuncAttributeMaxDynamicSharedMemorySize,
                         GEMM_SMEM);
    cudaFuncSetAttribute(gemm_out, cudaFuncAttributeMaxDynamicSharedMemorySize,
                         GEMM_SMEM);
    gemm_qkv<<<dim3(D_EMB / BN, T_SEQ / BM, 3), 128, GEMM_SMEM>>>(xf, wq, wk, wv,
                                                                  qf, kf, vf);

    cudaFuncSetAttribute(attn_mma, cudaFuncAttributeMaxDynamicSharedMemorySize,
                         ATTN_SMEM);
    attn_mma<<<dim3(T_SEQ / 128, NHEADS), 128, ATTN_SMEM>>>(qf, kf, vf, rf);

    gemm_out<<<dim3(D_EMB / BN, T_SEQ / BM), 128, GEMM_SMEM>>>(rf, wo, out);
}

// round 17
// speedup vs baseline: 1.1577x; 1.0111x over previous
#include <cuda_runtime.h>
#include <cuda_fp16.h>
#include <stdint.h>
#include <math.h>

#define T_SEQ 2048
#define D_EMB 2048
#define HD    128
#define NHEADS 16
// Q scale folded with log2(e): softmax computed in base-2 units.
#define QK_SCALE2 0.12753138106334646f  // (1/sqrt(128)) * log2(e)
#define WSCALE 256.0f
#define INV_WSCALE (1.0f / 256.0f)

// ---------------- scratch (no allocs allowed) ----------------
__device__ __half g_Xf[T_SEQ * D_EMB];
__device__ __half g_Rf[T_SEQ * D_EMB];
// weights in NATURAL layout (x256, fp16): Wq/Wk/Wv = [n][k][j], Wo = [k][j]
__device__ __half g_Wq[D_EMB * D_EMB];
__device__ __half g_Wk[D_EMB * D_EMB];
__device__ __half g_Wv[D_EMB * D_EMB];
__device__ __half g_Wo[D_EMB * D_EMB];
__device__ __half g_Qf[T_SEQ * D_EMB];
__device__ __half g_Kf[T_SEQ * D_EMB];
__device__ __half g_Vf[T_SEQ * D_EMB];

// ---------------- PTX helpers (base sm_103-legal only) ----------------
__device__ __forceinline__ uint32_t smem_u32(const void* p) {
    uint32_t a;
    asm("{ .reg .u64 t; cvta.to.shared.u64 t, %1; cvt.u32.u64 %0, t; }"
        : "=r"(a) : "l"(p));
    return a;
}
#define CP_ASYNC16(dst, src) \
    asm volatile("cp.async.cg.shared.global [%0], [%1], 16;" :: "r"(dst), "l"(src))
#define CP_COMMIT() asm volatile("cp.async.commit_group;" ::: "memory")
#define CP_WAIT(n) asm volatile("cp.async.wait_group %0;" :: "n"(n) : "memory")

__device__ __forceinline__ void ldsm_x4(uint32_t& r0, uint32_t& r1, uint32_t& r2,
                                        uint32_t& r3, uint32_t addr) {
    asm volatile("ldmatrix.sync.aligned.m8n8.x4.shared.b16 {%0,%1,%2,%3}, [%4];"
                 : "=r"(r0), "=r"(r1), "=r"(r2), "=r"(r3) : "r"(addr));
}
__device__ __forceinline__ void ldsm_x4_t(uint32_t& r0, uint32_t& r1, uint32_t& r2,
                                          uint32_t& r3, uint32_t addr) {
    asm volatile(
        "ldmatrix.sync.aligned.m8n8.x4.trans.shared.b16 {%0,%1,%2,%3}, [%4];"
        : "=r"(r0), "=r"(r1), "=r"(r2), "=r"(r3) : "r"(addr));
}
__device__ __forceinline__ void mma16816(float* c, const uint32_t* a,
                                         const uint32_t* b) {
    asm volatile(
        "mma.sync.aligned.m16n8k16.row.col.f32.f16.f16.f32 "
        "{%0,%1,%2,%3}, {%4,%5,%6,%7}, {%8,%9}, {%0,%1,%2,%3};"
        : "+f"(c[0]), "+f"(c[1]), "+f"(c[2]), "+f"(c[3])
        : "r"(a[0]), "r"(a[1]), "r"(a[2]), "r"(a[3]), "r"(b[0]), "r"(b[1]));
}
__device__ __forceinline__ uint32_t pack_f16(float x, float y) {
    __half2 h = __floats2half2_rn(x, y);
    return *reinterpret_cast<uint32_t*>(&h);
}

// ---------------- merged conversion kernel (pure streaming) ----------------
__global__ __launch_bounds__(256) void convAll(
    const float* __restrict__ X, const float* __restrict__ Wq,
    const float* __restrict__ Wk, const float* __restrict__ Wv,
    const float* __restrict__ Wo, __half* __restrict__ Xh,
    __half* __restrict__ Hq, __half* __restrict__ Hk,
    __half* __restrict__ Hv, __half* __restrict__ Ho) {
    const int z = blockIdx.y;
    const float* S = (z == 0) ? X : (z == 1) ? Wq : (z == 2) ? Wk
                     : (z == 3) ? Wv : Wo;
    __half* D = (z == 0) ? Xh : (z == 1) ? Hq : (z == 2) ? Hk
                : (z == 3) ? Hv : Ho;
    const float sc = (z == 0) ? 1.0f : WSCALE;
    const int i = blockIdx.x * 256 + threadIdx.x;
    float4 v = reinterpret_cast<const float4*>(S)[i];
    __half f[4] = {__float2half_rn(v.x * sc), __float2half_rn(v.y * sc),
                   __float2half_rn(v.z * sc), __float2half_rn(v.w * sc)};
    reinterpret_cast<uint2*>(D)[i] = *reinterpret_cast<uint2*>(f);
}

// ---------------- 1-pass fp16 HMMA GEMM (6-stage, frag-pipelined) ------------
#define BM 128
#define BN 128
#define BK 32
#define STAGE_B 16384
#define NSTAGE 6
#define GEMM_SMEM (NSTAGE * STAGE_B)

__device__ __forceinline__ uint32_t swzA(uint32_t base, int row, int chunk) {
    return base + (((row << 2) + (chunk ^ ((row >> 1) & 3))) << 4);
}
__device__ __forceinline__ uint32_t swzB(uint32_t base, int row, int chunk) {
    return base + (((row << 4) + (chunk ^ (row & 7))) << 4);
}

__device__ __forceinline__ void stage_all(uint32_t sbase, const __half* Af,
                                          const __half* Bp, int bstride, int bm,
                                          int k0, int tid) {
#pragma unroll
    for (int u = tid; u < 512; u += 128) {
        const int row = u >> 2, ch = u & 3;
        CP_ASYNC16(swzA(sbase, row, ch),
                   Af + (size_t)(bm + row) * D_EMB + k0 + ch * 8);
    }
#pragma unroll
    for (int u = tid; u < 512; u += 128) {
        const int row = u >> 4, ch = u & 15;
        CP_ASYNC16(swzB(sbase + 8192, row, ch),
                   Bp + (size_t)(k0 + row) * bstride + ch * 8);
    }
}

// fragment loads for one kk group (k16 slice)
__device__ __forceinline__ void load_frags(uint32_t sX, uint32_t sB, int kk,
                                           int wm, int wn, int lr, int lg,
                                           uint32_t a4[4][4], uint32_t b4[8][2]) {
#pragma unroll
    for (int mt = 0; mt < 4; mt++) {
        const int row = wm * 64 + mt * 16 + lr + (lg & 1) * 8;
        const int ch = kk * 2 + (lg >> 1);
        ldsm_x4(a4[mt][0], a4[mt][1], a4[mt][2], a4[mt][3], swzA(sX, row, ch));
    }
#pragma unroll
    for (int nt = 0; nt < 8; nt += 2) {
        uint32_t v0, v1, v2, v3;
        const int row = kk * 16 + (lg & 1) * 8 + lr;
        const int ch = wn * 8 + nt + (lg >> 1);
        ldsm_x4_t(v0, v1, v2, v3, swzB(sB, row, ch));
        b4[nt][0] = v0;
        b4[nt][1] = v1;
        b4[nt + 1][0] = v2;
        b4[nt + 1][1] = v3;
    }
}

__device__ __forceinline__ void gemm_core1(
    uint32_t sb, const __half* Af, const __half* Bp, int bstride, int bm,
    int tid, float acc[4][8][4]) {
    const int lane = tid & 31;
    const int wid = tid >> 5;
    const int wm = wid & 1;
    const int wn = wid >> 1;
    const int lr = lane & 7;
    const int lg = lane >> 3;

#pragma unroll
    for (int mt = 0; mt < 4; mt++)
#pragma unroll
        for (int nt = 0; nt < 8; nt++)
#pragma unroll
            for (int e = 0; e < 4; e++) acc[mt][nt][e] = 0.0f;

    const int NITER = D_EMB / BK;  // 64
#pragma unroll
    for (int s = 0; s < NSTAGE - 1; s++) {
        stage_all(sb + s * STAGE_B, Af, Bp, bstride, bm, s * BK, tid);
        CP_COMMIT();
    }

    uint32_t a4[2][4][4], b4[2][8][2];
    for (int c = 0; c < NITER; c++) {
        CP_WAIT(4);
        __syncthreads();
        if (c + NSTAGE - 1 < NITER)
            stage_all(sb + ((c + NSTAGE - 1) % NSTAGE) * STAGE_B, Af, Bp,
                      bstride, bm, (c + NSTAGE - 1) * BK, tid);
        CP_COMMIT();

        const uint32_t sX = sb + (c % NSTAGE) * STAGE_B;
        const uint32_t sB = sX + 8192;

        // software-pipelined: kk=1 ldsm issues before kk=0 mma chain
        load_frags(sX, sB, 0, wm, wn, lr, lg, a4[0], b4[0]);
        load_frags(sX, sB, 1, wm, wn, lr, lg, a4[1], b4[1]);
#pragma unroll
        for (int kk = 0; kk < 2; kk++)
#pragma unroll
            for (int mt = 0; mt < 4; mt++)
#pragma unroll
                for (int nt = 0; nt < 8; nt++)
                    mma16816(acc[mt][nt], a4[kk][mt], b4[kk][nt]);
    }
    CP_WAIT(0);
    __syncthreads();
}

// fused QKV: z=0 -> Q (scaled by QK_SCALE2); z=1 -> K; z=2 -> V
__global__ __launch_bounds__(128, 2) void gemm_qkv(
    const __half* __restrict__ Xf, const __half* __restrict__ Wq,
    const __half* __restrict__ Wk, const __half* __restrict__ Wv,
    __half* __restrict__ Qf, __half* __restrict__ Kf, __half* __restrict__ Vf) {
    extern __shared__ char sm[];
    const uint32_t sb = smem_u32(sm);
    const int tid = threadIdx.x;
    const int lane = tid & 31;
    const int wid = tid >> 5;
    const int z = blockIdx.z;
    const int bm = blockIdx.y * BM;
    const int bn = blockIdx.x * BN;

    const __half* W = (z == 0) ? Wq : (z == 1) ? Wk : Wv;
    const __half* Bp = W + (size_t)(bn >> 7) * D_EMB * HD;  // BN == HD

    float acc[4][8][4];
    gemm_core1(sb, Xf, Bp, HD, bm, tid, acc);

    const int wm = wid & 1;
    const int wn = wid >> 1;
    __half* Dst = (z == 0) ? Qf : (z == 1) ? Kf : Vf;
    const float s = (z == 0) ? (QK_SCALE2 * INV_WSCALE) : INV_WSCALE;
#pragma unroll
    for (int mt = 0; mt < 4; mt++) {
        const int row = bm + wm * 64 + mt * 16 + (lane >> 2);
#pragma unroll
        for (int nt = 0; nt < 8; nt++) {
            const int col = bn + wn * 64 + nt * 8 + (lane & 3) * 2;
            *reinterpret_cast<uint32_t*>(&Dst[(size_t)row * D_EMB + col]) =
                pack_f16(acc[mt][nt][0] * s, acc[mt][nt][1] * s);
            *reinterpret_cast<uint32_t*>(&Dst[(size_t)(row + 8) * D_EMB + col]) =
                pack_f16(acc[mt][nt][2] * s, acc[mt][nt][3] * s);
        }
    }
}

// out-projection: fp32 output
__global__ __launch_bounds__(128, 2) void gemm_out(
    const __half* __restrict__ Af, const __half* __restrict__ Wo,
    float* __restrict__ C) {
    extern __shared__ char sm[];
    const uint32_t sb = smem_u32(sm);
    const int tid = threadIdx.x;
    const int lane = tid & 31;
    const int wid = tid >> 5;
    const int bm = blockIdx.y * BM;
    const int bn = blockIdx.x * BN;

    const __half* Bp = Wo + bn;

    float acc[4][8][4];
    gemm_core1(sb, Af, Bp, D_EMB, bm, tid, acc);

    const int wm = wid & 1;
    const int wn = wid >> 1;
#pragma unroll
    for (int mt = 0; mt < 4; mt++) {
        const int row = bm + wm * 64 + mt * 16 + (lane >> 2);
#pragma unroll
        for (int nt = 0; nt < 8; nt++) {
            const int col = bn + wn * 64 + nt * 8 + (lane & 3) * 2;
            *reinterpret_cast<float2*>(&C[(size_t)row * D_EMB + col]) =
                make_float2(acc[mt][nt][0] * INV_WSCALE, acc[mt][nt][1] * INV_WSCALE);
            *reinterpret_cast<float2*>(&C[(size_t)(row + 8) * D_EMB + col]) =
                make_float2(acc[mt][nt][2] * INV_WSCALE, acc[mt][nt][3] * INV_WSCALE);
        }
    }
}

// ---------------- fp16 HMMA flash attention (base-2 softmax) ----------------
#define ATTN_SMEM 65536

__global__ __launch_bounds__(128, 2) void attn_mma(
    const __half* __restrict__ Qf, const __half* __restrict__ Kf,
    const __half* __restrict__ Vf, __half* __restrict__ Rf) {
    extern __shared__ char sm[];
    const uint32_t sb = smem_u32(sm);
    const uint32_t sQ = sb;
    const uint32_t sK = sb + 32768;
    const uint32_t sV = sb + 49152;

    const int n = blockIdx.y;
    const int m0 = blockIdx.x * 128;
    const int tid = threadIdx.x;
    const int lane = tid & 31;
    const int w = tid >> 5;
    const int lr = lane & 7;
    const int lg = lane >> 3;

    for (int u = tid; u < 2048; u += 128) {
        const int row = u >> 4, ch = u & 15;
        const uint32_t d = (uint32_t)((row * 16 + (ch ^ (row & 7))) * 16);
        CP_ASYNC16(sQ + d, Qf + (size_t)(m0 + row) * D_EMB + n * HD + ch * 8);
    }
    CP_COMMIT();
    for (int u = tid; u < 1024; u += 128) {
        const int row = u >> 4, ch = u & 15;
        const uint32_t d = (uint32_t)((row * 16 + (ch ^ (row & 7))) * 16);
        CP_ASYNC16(sK + d, Kf + (size_t)row * D_EMB + n * HD + ch * 8);
    }
    CP_COMMIT();
    for (int u = tid; u < 1024; u += 128) {
        const int row = u >> 4, ch = u & 15;
        const uint32_t d = (uint32_t)((row * 16 + (ch ^ (row & 7))) * 16);
        CP_ASYNC16(sV + d, Vf + (size_t)row * D_EMB + n * HD + ch * 8);
    }
    CP_COMMIT();

    float acc[2][16][4];
#pragma unroll
    for (int mt = 0; mt < 2; mt++)
#pragma unroll
        for (int ht = 0; ht < 16; ht++)
#pragma unroll
            for (int e = 0; e < 4; e++) acc[mt][ht][e] = 0.0f;
    float M0[2] = {-1e30f, -1e30f}, M1[2] = {-1e30f, -1e30f};
    float L0[2] = {0.0f, 0.0f}, L1[2] = {0.0f, 0.0f};

    const int NT = T_SEQ / 64;
    for (int it = 0; it < NT; it++) {
        CP_WAIT(1);
        __syncthreads();

        float c[2][8][4];
#pragma unroll
        for (int mt = 0; mt < 2; mt++)
#pragma unroll
            for (int t = 0; t < 8; t++)
#pragma unroll
                for (int e = 0; e < 4; e++) c[mt][t][e] = 0.0f;

#pragma unroll
        for (int kk = 0; kk < 8; kk++) {
            uint32_t q4[2][4];
#pragma unroll
            for (int mt = 0; mt < 2; mt++) {
                const int row = w * 32 + mt * 16 + lr + (lg & 1) * 8;
                const int ch = kk * 2 + (lg >> 1);
                const uint32_t a = (uint32_t)((row * 16 + (ch ^ (row & 7))) * 16);
                ldsm_x4(q4[mt][0], q4[mt][1], q4[mt][2], q4[mt][3], sQ + a);
            }
#pragma unroll
            for (int np = 0; np < 4; np++) {
                uint32_t k4[4];
                const int row = np * 16 + lr + (lg >> 1) * 8;
                const int ch = kk * 2 + (lg & 1);
                const uint32_t a = (uint32_t)((row * 16 + (ch ^ (row & 7))) * 16);
                ldsm_x4(k4[0], k4[1], k4[2], k4[3], sK + a);
#pragma unroll
                for (int mt = 0; mt < 2; mt++) {
                    mma16816(c[mt][np * 2],     q4[mt], &k4[0]);
                    mma16816(c[mt][np * 2 + 1], q4[mt], &k4[2]);
                }
            }
        }
        __syncthreads();

        if (it + 1 < NT) {
            for (int u = tid; u < 1024; u += 128) {
                const int row = u >> 4, ch = u & 15;
                const uint32_t d = (uint32_t)((row * 16 + (ch ^ (row & 7))) * 16);
                CP_ASYNC16(sK + d, Kf + (size_t)((it + 1) * 64 + row) * D_EMB +
                                       n * HD + ch * 8);
            }
            CP_COMMIT();
        }

        // ---- online softmax in base-2 units ----
#pragma unroll
        for (int mt = 0; mt < 2; mt++) {
            float mx0 = -1e30f, mx1 = -1e30f;
#pragma unroll
            for (int t = 0; t < 8; t++) {
                mx0 = fmaxf(mx0, fmaxf(c[mt][t][0], c[mt][t][1]));
                mx1 = fmaxf(mx1, fmaxf(c[mt][t][2], c[mt][t][3]));
            }
            mx0 = fmaxf(mx0, __shfl_xor_sync(0xffffffffu, mx0, 1));
            mx0 = fmaxf(mx0, __shfl_xor_sync(0xffffffffu, mx0, 2));
            mx1 = fmaxf(mx1, __shfl_xor_sync(0xffffffffu, mx1, 1));
            mx1 = fmaxf(mx1, __shfl_xor_sync(0xffffffffu, mx1, 2));

            const float Mn0 = fmaxf(M0[mt], mx0), Mn1 = fmaxf(M1[mt], mx1);
            const float a0 = exp2f(M0[mt] - Mn0), a1 = exp2f(M1[mt] - Mn1);
            float sum0 = 0.0f, sum1 = 0.0f;
#pragma unroll
            for (int t = 0; t < 8; t++) {
                c[mt][t][0] = exp2f(c[mt][t][0] - Mn0);
                c[mt][t][1] = exp2f(c[mt][t][1] - Mn0);
                c[mt][t][2] = exp2f(c[mt][t][2] - Mn1);
                c[mt][t][3] = exp2f(c[mt][t][3] - Mn1);
                sum0 += c[mt][t][0] + c[mt][t][1];
                sum1 += c[mt][t][2] + c[mt][t][3];
            }
            sum0 += __shfl_xor_sync(0xffffffffu, sum0, 1);
            sum0 += __shfl_xor_sync(0xffffffffu, sum0, 2);
            sum1 += __shfl_xor_sync(0xffffffffu, sum1, 1);
            sum1 += __shfl_xor_sync(0xffffffffu, sum1, 2);
            L0[mt] = L0[mt] * a0 + sum0;
            L1[mt] = L1[mt] * a1 + sum1;
            M0[mt] = Mn0;
            M1[mt] = Mn1;
#pragma unroll
            for (int ht = 0; ht < 16; ht++) {
                acc[mt][ht][0] *= a0;
                acc[mt][ht][1] *= a0;
                acc[mt][ht][2] *= a1;
                acc[mt][ht][3] *= a1;
            }
        }

        if (it + 1 < NT) {
            CP_WAIT(1);
        } else {
            CP_WAIT(0);
        }
        __syncthreads();

#pragma unroll
        for (int kk = 0; kk < 4; kk++) {
            uint32_t ap[2][4];
#pragma unroll
            for (int mt = 0; mt < 2; mt++) {
                const int t0 = kk * 2, t1 = kk * 2 + 1;
                ap[mt][0] = pack_f16(c[mt][t0][0], c[mt][t0][1]);
                ap[mt][1] = pack_f16(c[mt][t0][2], c[mt][t0][3]);
                ap[mt][2] = pack_f16(c[mt][t1][0], c[mt][t1][1]);
                ap[mt][3] = pack_f16(c[mt][t1][2], c[mt][t1][3]);
            }
#pragma unroll
            for (int hq = 0; hq < 8; hq++) {
                uint32_t v4[4];
                const int row = kk * 16 + (lg & 1) * 8 + lr;
                const int ch = hq * 2 + (lg >> 1);
                const uint32_t a = (uint32_t)((row * 16 + (ch ^ (row & 7))) * 16);
                ldsm_x4_t(v4[0], v4[1], v4[2], v4[3], sV + a);
#pragma unroll
                for (int mt = 0; mt < 2; mt++) {
                    mma16816(acc[mt][hq * 2],     ap[mt], &v4[0]);
                    mma16816(acc[mt][hq * 2 + 1], ap[mt], &v4[2]);
                }
            }
        }
        __syncthreads();

        if (it + 1 < NT) {
            for (int u = tid; u < 1024; u += 128) {
                const int row = u >> 4, ch = u & 15;
                const uint32_t d = (uint32_t)((row * 16 + (ch ^ (row & 7))) * 16);
                CP_ASYNC16(sV + d, Vf + (size_t)((it + 1) * 64 + row) * D_EMB +
                                       n * HD + ch * 8);
            }
            CP_COMMIT();
        }
    }

#pragma unroll
    for (int mt = 0; mt < 2; mt++) {
        const float i0 = 1.0f / L0[mt], i1 = 1.0f / L1[mt];
        const int rowg = m0 + w * 32 + mt * 16 + (lane >> 2);
#pragma unroll
        for (int ht = 0; ht < 16; ht++) {
            const int col = n * HD + ht * 8 + (lane & 3) * 2;
            *reinterpret_cast<uint32_t*>(&Rf[(size_t)rowg * D_EMB + col]) =
                pack_f16(acc[mt][ht][0] * i0, acc[mt][ht][1] * i0);
            *reinterpret_cast<uint32_t*>(&Rf[(size_t)(rowg + 8) * D_EMB + col]) =
                pack_f16(acc[mt][ht][2] * i1, acc[mt][ht][3] * i1);
        }
    }
}

// ---------------------------------------------------------------------------
extern "C" void kernel_launch(void* const* d_in, const int* in_sizes, int n_in,
                              void* d_out, int out_size) {
    const float* X  = (const float*)d_in[0];
    const float* Wq = (const float*)d_in[1];
    const float* Wk = (const float*)d_in[2];
    const float* Wv = (const float*)d_in[3];
    const float* Wo = (const float*)d_in[4];
    float* out = (float*)d_out;

    __half *xf, *rf, *qf, *kf, *vf, *wq, *wk, *wv, *wo;
    cudaGetSymbolAddress((void**)&xf, g_Xf);
    cudaGetSymbolAddress((void**)&rf, g_Rf);
    cudaGetSymbolAddress((void**)&qf, g_Qf);
    cudaGetSymbolAddress((void**)&kf, g_Kf);
    cudaGetSymbolAddress((void**)&vf, g_Vf);
    cudaGetSymbolAddress((void**)&wq, g_Wq);
    cudaGetSymbolAddress((void**)&wk, g_Wk);
    cudaGetSymbolAddress((void**)&wv, g_Wv);
    cudaGetSymbolAddress((void**)&wo, g_Wo);

    const int NELE4 = T_SEQ * D_EMB / 4 / 256;

    convAll<<<dim3(NELE4, 5), 256>>>(X, Wq, Wk, Wv, Wo, xf, wq, wk, wv, wo);

    cudaFuncSetAttribute(gemm_qkv, cudaFuncAttributeMaxDynamicSharedMemorySize,
                         GEMM_SMEM);
    cudaFuncSetAttribute(gemm_out, cudaFuncAttributeMaxDynamicSharedMemorySize,
                         GEMM_SMEM);
    gemm_qkv<<<dim3(D_EMB / BN, T_SEQ / BM, 3), 128, GEMM_SMEM>>>(xf, wq, wk, wv,
                                                                  qf, kf, vf);

    cudaFuncSetAttribute(attn_mma, cudaFuncAttributeMaxDynamicSharedMemorySize,
                         ATTN_SMEM);
    attn_mma<<<dim3(T_SEQ / 128, NHEADS), 128, ATTN_SMEM>>>(qf, kf, vf, rf);

    gemm_out<<<dim3(D_EMB / BN, T_SEQ / BM), 128, GEMM_SMEM>>>(rf, wo, out);
}